// round 1
// baseline (speedup 1.0000x reference)
#include <cuda_runtime.h>
#include <cuda_bf16.h>

#define BB 16
#define NN 576
#define DD 1024
#define HH 16
#define HD 64

// ---------------- scratch (static device globals; no allocation) ----------------
__device__ float g_qk[(long)BB * NN * 2 * DD];        // [B,N,2D]  75.5 MB
__device__ float g_v[(long)BB * NN * DD];             // [B,N,D]   37.7 MB
__device__ float g_pos[(long)HH * NN * NN];           // [H,N,N]   21 MB
__device__ float g_attn[(long)BB * HH * NN * NN];     // [B,H,N,N] 340 MB
__device__ float g_o[(long)BB * NN * DD];             // [B,N,D]   37.7 MB

// ---------------- generic 128x128x8 SGEMM: C = A[M,K] @ W[K,Nc] (+bias) --------
template <bool BIAS>
__global__ __launch_bounds__(256) void sgemm128(const float* __restrict__ A,
                                                const float* __restrict__ W,
                                                const float* __restrict__ bias,
                                                float* __restrict__ C,
                                                int M, int K, int Ncols) {
    __shared__ float As[8][128];
    __shared__ float Bs[8][128];
    const int tid = threadIdx.x;
    const int bm = blockIdx.y * 128, bn = blockIdx.x * 128;
    const int tx = tid & 15, ty = tid >> 4;

    // A tile loader: 128 rows x 8 cols = 256 float4, one per thread
    const int ar = tid >> 1;
    const int ac = (tid & 1) * 4;
    // B tile loader: 8 rows x 128 cols = 256 float4, one per thread
    const int br = tid >> 5;
    const int bc = (tid & 31) * 4;

    const float* Aptr = A + (long)(bm + ar) * K + ac;
    const float* Wptr = W + (long)br * Ncols + bn + bc;

    float acc[8][8];
#pragma unroll
    for (int i = 0; i < 8; i++)
#pragma unroll
        for (int j = 0; j < 8; j++) acc[i][j] = 0.0f;

    for (int k0 = 0; k0 < K; k0 += 8) {
        float4 a4 = *(const float4*)(Aptr + k0);
        As[ac + 0][ar] = a4.x;
        As[ac + 1][ar] = a4.y;
        As[ac + 2][ar] = a4.z;
        As[ac + 3][ar] = a4.w;
        *(float4*)(&Bs[br][bc]) = *(const float4*)(Wptr + (long)k0 * Ncols);
        __syncthreads();
#pragma unroll
        for (int kk = 0; kk < 8; kk++) {
            float af[8], bf[8];
#pragma unroll
            for (int i = 0; i < 8; i++) af[i] = As[kk][ty + 16 * i];
#pragma unroll
            for (int j = 0; j < 8; j++) bf[j] = Bs[kk][tx + 16 * j];
#pragma unroll
            for (int i = 0; i < 8; i++)
#pragma unroll
                for (int j = 0; j < 8; j++) acc[i][j] += af[i] * bf[j];
        }
        __syncthreads();
    }

#pragma unroll
    for (int i = 0; i < 8; i++) {
        const long m = bm + ty + 16 * i;
#pragma unroll
        for (int j = 0; j < 8; j++) {
            const int n = bn + tx + 16 * j;
            float v = acc[i][j];
            if (BIAS) v += bias[n];
            C[m * Ncols + n] = v;
        }
    }
}

// ---------------- positional softmax: pos[h,n,:] = softmax(rel@W_pos+b) --------
__global__ __launch_bounds__(256) void pos_kernel(const float* __restrict__ rel,
                                                  const float* __restrict__ Wp,
                                                  const float* __restrict__ bp,
                                                  float* __restrict__ pos) {
    const int n = blockIdx.x, h = blockIdx.y, tid = threadIdx.x;
    __shared__ float red[8];
    __shared__ float bcv;
    const float w0 = Wp[h], w1 = Wp[HH + h], w2 = Wp[2 * HH + h], bb = bp[h];
    const float* r = rel + (long)n * NN * 3;

    float s0, s1, s2 = -1e30f;
    {
        const float* p = r + tid * 3;
        s0 = p[0] * w0 + p[1] * w1 + p[2] * w2 + bb;
        p = r + (tid + 256) * 3;
        s1 = p[0] * w0 + p[1] * w1 + p[2] * w2 + bb;
        if (tid < 64) {
            p = r + (tid + 512) * 3;
            s2 = p[0] * w0 + p[1] * w1 + p[2] * w2 + bb;
        }
    }
    float mx = fmaxf(fmaxf(s0, s1), s2);
#pragma unroll
    for (int o = 16; o; o >>= 1) mx = fmaxf(mx, __shfl_xor_sync(~0u, mx, o));
    if ((tid & 31) == 0) red[tid >> 5] = mx;
    __syncthreads();
    if (tid == 0) {
        float m = red[0];
        for (int i = 1; i < 8; i++) m = fmaxf(m, red[i]);
        bcv = m;
    }
    __syncthreads();
    mx = bcv;
    float e0 = expf(s0 - mx), e1 = expf(s1 - mx);
    float e2 = (tid < 64) ? expf(s2 - mx) : 0.0f;
    float sum = e0 + e1 + e2;
#pragma unroll
    for (int o = 16; o; o >>= 1) sum += __shfl_xor_sync(~0u, sum, o);
    __syncthreads();
    if ((tid & 31) == 0) red[tid >> 5] = sum;
    __syncthreads();
    if (tid == 0) {
        float s = 0.f;
        for (int i = 0; i < 8; i++) s += red[i];
        bcv = 1.0f / s;
    }
    __syncthreads();
    const float inv = bcv;
    float* out = pos + ((long)h * NN + n) * NN;
    out[tid] = e0 * inv;
    out[tid + 256] = e1 * inv;
    if (tid < 64) out[tid + 512] = e2 * inv;
}

// ---------------- scores: S[b,h] = q @ k^T * scale -----------------------------
__global__ __launch_bounds__(256) void score_kernel(const float* __restrict__ qk,
                                                    float* __restrict__ attn) {
    const int bh = blockIdx.z;
    const int b = bh >> 4, h = bh & 15;
    const int n0 = blockIdx.y * 64, m0 = blockIdx.x * 64;
    __shared__ float qs[64][65];
    __shared__ float ks[64][65];
    const int tid = threadIdx.x, tx = tid & 15, ty = tid >> 4;

    const float* qbase = qk + (long)b * NN * 2048 + h * 64;
    const float* kbase = qbase + 1024;
    for (int idx = tid; idx < 64 * 16; idx += 256) {
        const int r = idx >> 4, c4 = (idx & 15) * 4;
        float4 a = *(const float4*)(qbase + (long)(n0 + r) * 2048 + c4);
        qs[r][c4] = a.x; qs[r][c4 + 1] = a.y; qs[r][c4 + 2] = a.z; qs[r][c4 + 3] = a.w;
        float4 c = *(const float4*)(kbase + (long)(m0 + r) * 2048 + c4);
        ks[r][c4] = c.x; ks[r][c4 + 1] = c.y; ks[r][c4 + 2] = c.z; ks[r][c4 + 3] = c.w;
    }
    __syncthreads();

    float acc[4][4];
#pragma unroll
    for (int i = 0; i < 4; i++)
#pragma unroll
        for (int j = 0; j < 4; j++) acc[i][j] = 0.0f;

#pragma unroll 8
    for (int d = 0; d < 64; d++) {
        float a[4], bf[4];
#pragma unroll
        for (int i = 0; i < 4; i++) a[i] = qs[ty + 16 * i][d];
#pragma unroll
        for (int j = 0; j < 4; j++) bf[j] = ks[tx + 16 * j][d];
#pragma unroll
        for (int i = 0; i < 4; i++)
#pragma unroll
            for (int j = 0; j < 4; j++) acc[i][j] += a[i] * bf[j];
    }

    const float scale = 0.125f;
#pragma unroll
    for (int i = 0; i < 4; i++) {
        float* dst = attn + ((long)bh * NN + n0 + ty + 16 * i) * NN + m0;
#pragma unroll
        for (int j = 0; j < 4; j++) dst[tx + 16 * j] = acc[i][j] * scale;
    }
}

// ---------------- softmax + gated mix + renorm (in place on g_attn) ------------
__global__ __launch_bounds__(256) void mix_kernel(const float* __restrict__ pos,
                                                  const float* __restrict__ gating,
                                                  float* __restrict__ attn) {
    const int n = blockIdx.x;
    const int bh = blockIdx.y;
    const int h = bh & 15;
    const int tid = threadIdx.x;
    __shared__ float red[8];
    __shared__ float bcv;

    float* arow = attn + ((long)bh * NN + n) * NN;
    const float* prow = pos + ((long)h * NN + n) * NN;
    const float g = 1.0f / (1.0f + expf(-gating[h]));

    float s0 = arow[tid];
    float s1 = arow[tid + 256];
    float s2 = (tid < 64) ? arow[tid + 512] : -1e30f;

    float mx = fmaxf(fmaxf(s0, s1), s2);
#pragma unroll
    for (int o = 16; o; o >>= 1) mx = fmaxf(mx, __shfl_xor_sync(~0u, mx, o));
    if ((tid & 31) == 0) red[tid >> 5] = mx;
    __syncthreads();
    if (tid == 0) {
        float m = red[0];
        for (int i = 1; i < 8; i++) m = fmaxf(m, red[i]);
        bcv = m;
    }
    __syncthreads();
    mx = bcv;

    float e0 = expf(s0 - mx), e1 = expf(s1 - mx);
    float e2 = (tid < 64) ? expf(s2 - mx) : 0.0f;
    float sum = e0 + e1 + e2;
#pragma unroll
    for (int o = 16; o; o >>= 1) sum += __shfl_xor_sync(~0u, sum, o);
    __syncthreads();
    if ((tid & 31) == 0) red[tid >> 5] = sum;
    __syncthreads();
    if (tid == 0) {
        float s = 0.f;
        for (int i = 0; i < 8; i++) s += red[i];
        bcv = 1.0f / s;
    }
    __syncthreads();
    const float inv = bcv;

    const float og = 1.0f - g;
    float a0 = og * e0 * inv + g * prow[tid];
    float a1 = og * e1 * inv + g * prow[tid + 256];
    float a2 = (tid < 64) ? (og * e2 * inv + g * prow[tid + 512]) : 0.0f;

    float tot = a0 + a1 + a2;
#pragma unroll
    for (int o = 16; o; o >>= 1) tot += __shfl_xor_sync(~0u, tot, o);
    __syncthreads();
    if ((tid & 31) == 0) red[tid >> 5] = tot;
    __syncthreads();
    if (tid == 0) {
        float s = 0.f;
        for (int i = 0; i < 8; i++) s += red[i];
        bcv = 1.0f / s;
    }
    __syncthreads();
    const float inv2 = bcv;

    arow[tid] = a0 * inv2;
    arow[tid + 256] = a1 * inv2;
    if (tid < 64) arow[tid + 512] = a2 * inv2;
}

// ---------------- O[b,h] = attn[b,h] @ v[b,h] ----------------------------------
__global__ __launch_bounds__(256) void av_kernel(const float* __restrict__ attn,
                                                 const float* __restrict__ v,
                                                 float* __restrict__ o) {
    const int bh = blockIdx.y;
    const int b = bh >> 4, h = bh & 15;
    const int n0 = blockIdx.x * 64;
    __shared__ float as[64][65];
    __shared__ float vs[64][64];
    const int tid = threadIdx.x, tx = tid & 15, ty = tid >> 4;

    float acc[4][4];
#pragma unroll
    for (int i = 0; i < 4; i++)
#pragma unroll
        for (int j = 0; j < 4; j++) acc[i][j] = 0.0f;

    for (int m0 = 0; m0 < NN; m0 += 64) {
        for (int idx = tid; idx < 64 * 16; idx += 256) {
            const int r = idx >> 4, c4 = (idx & 15) * 4;
            float4 a = *(const float4*)(attn + ((long)bh * NN + n0 + r) * NN + m0 + c4);
            as[r][c4] = a.x; as[r][c4 + 1] = a.y; as[r][c4 + 2] = a.z; as[r][c4 + 3] = a.w;
            *(float4*)(&vs[r][c4]) =
                *(const float4*)(v + ((long)(b * NN + m0 + r)) * DD + h * 64 + c4);
        }
        __syncthreads();
#pragma unroll 8
        for (int mm = 0; mm < 64; mm++) {
            float a[4], bf[4];
#pragma unroll
            for (int i = 0; i < 4; i++) a[i] = as[ty + 16 * i][mm];
#pragma unroll
            for (int j = 0; j < 4; j++) bf[j] = vs[mm][tx + 16 * j];
#pragma unroll
            for (int i = 0; i < 4; i++)
#pragma unroll
                for (int j = 0; j < 4; j++) acc[i][j] += a[i] * bf[j];
        }
        __syncthreads();
    }

#pragma unroll
    for (int i = 0; i < 4; i++) {
        float* dst = o + ((long)(b * NN + n0 + ty + 16 * i)) * DD + h * 64;
#pragma unroll
        for (int j = 0; j < 4; j++) dst[tx + 16 * j] = acc[i][j];
    }
}

// ---------------- launch ----------------
extern "C" void kernel_launch(void* const* d_in, const int* in_sizes, int n_in,
                              void* d_out, int out_size) {
    const float* x      = (const float*)d_in[0];  // [B,N,D]
    const float* W_qk   = (const float*)d_in[1];  // [D,2D]
    const float* W_v    = (const float*)d_in[2];  // [D,D]
    const float* W_proj = (const float*)d_in[3];  // [D,D]
    const float* b_proj = (const float*)d_in[4];  // [D]
    const float* W_pos  = (const float*)d_in[5];  // [3,H]
    const float* b_pos  = (const float*)d_in[6];  // [H]
    const float* gating = (const float*)d_in[7];  // [H]
    const float* rel    = (const float*)d_in[8];  // [N,N,3]
    float* out = (float*)d_out;

    float* qk;   cudaGetSymbolAddress((void**)&qk,   g_qk);
    float* vbuf; cudaGetSymbolAddress((void**)&vbuf, g_v);
    float* pos;  cudaGetSymbolAddress((void**)&pos,  g_pos);
    float* attn; cudaGetSymbolAddress((void**)&attn, g_attn);
    float* obuf; cudaGetSymbolAddress((void**)&obuf, g_o);

    const int M = BB * NN;  // 9216

    // 1) qk = x @ W_qk   [9216,1024]x[1024,2048]
    sgemm128<false><<<dim3(2 * DD / 128, M / 128), 256>>>(x, W_qk, nullptr, qk, M, DD, 2 * DD);
    // 2) v = x @ W_v
    sgemm128<false><<<dim3(DD / 128, M / 128), 256>>>(x, W_v, nullptr, vbuf, M, DD, DD);
    // 3) positional softmax
    pos_kernel<<<dim3(NN, HH), 256>>>(rel, W_pos, b_pos, pos);
    // 4) scores
    score_kernel<<<dim3(NN / 64, NN / 64, BB * HH), 256>>>(qk, attn);
    // 5) softmax + gated mix + renorm
    mix_kernel<<<dim3(NN, BB * HH), 256>>>(pos, gating, attn);
    // 6) attn @ v
    av_kernel<<<dim3(NN / 64, BB * HH), 256>>>(attn, vbuf, obuf);
    // 7) out = o @ W_proj + b_proj
    sgemm128<true><<<dim3(DD / 128, M / 128), 256>>>(obuf, W_proj, b_proj, out, M, DD, DD);
}

// round 2
// speedup vs baseline: 1.9275x; 1.9275x over previous
#include <cuda_runtime.h>
#include <cuda_bf16.h>
#include <cstdint>

#define BB 16
#define NN 576
#define DD 1024
#define HH 16
#define HD 64

// ---------------- scratch (static device globals; no allocation) ----------------
__device__ float g_qk[(long)BB * NN * 2 * DD];        // [B,N,2D]  75.5 MB
__device__ float g_v[(long)BB * NN * DD];             // [B,N,D]   37.7 MB
__device__ float g_pos[(long)HH * NN * NN];           // [H,N,N]   21 MB
__device__ float g_attn[(long)BB * HH * NN * NN];     // [B,H,N,N] 340 MB
__device__ float g_o[(long)BB * NN * DD];             // [B,N,D]   37.7 MB

// ---------------- tf32 helpers -------------------------------------------------
__device__ __forceinline__ float to_tf32(float x) {
    unsigned r;
    asm("cvt.rna.tf32.f32 %0, %1;" : "=r"(r) : "f"(x));
    return __uint_as_float(r);
}

__device__ __forceinline__ void mma_tf32(float& d0, float& d1, float& d2, float& d3,
                                         float a0, float a1, float a2, float a3,
                                         float b0, float b1) {
    asm volatile(
        "mma.sync.aligned.m16n8k8.row.col.f32.tf32.tf32.f32 "
        "{%0,%1,%2,%3}, {%4,%5,%6,%7}, {%8,%9}, {%0,%1,%2,%3};\n"
        : "+f"(d0), "+f"(d1), "+f"(d2), "+f"(d3)
        : "r"(__float_as_uint(a0)), "r"(__float_as_uint(a1)),
          "r"(__float_as_uint(a2)), "r"(__float_as_uint(a3)),
          "r"(__float_as_uint(b0)), "r"(__float_as_uint(b1)));
}

// ---------------- tf32 tensor-core GEMM: C = A[M,K] @ W[K,Nc] (+bias) ----------
// Block tile 128x128x32, 256 threads = 8 warps in 2(m) x 4(n), warp tile 64x32.
// Each warp: 4 m-atoms (m16) x 4 n-atoms (n8), mma.m16n8k8.
#define GBM 128
#define GBN 128
#define GBK 32

template <bool BIAS>
__global__ __launch_bounds__(256, 2) void gemm_tf32(const float* __restrict__ A,
                                                    const float* __restrict__ W,
                                                    const float* __restrict__ bias,
                                                    float* __restrict__ C,
                                                    int M, int K, int Ncols) {
    __shared__ float As[GBM][GBK + 4];   // [m][k], stride 36 -> frag bank = lane
    __shared__ float Bs[GBK][GBN + 8];   // [k][n], stride 136 -> frag bank = lane

    const int tid = threadIdx.x;
    const int warp = tid >> 5, lane = tid & 31;
    const int wm = (warp & 1) * 64;      // warp m offset in tile
    const int wn = (warp >> 1) * 32;     // warp n offset in tile
    const int gp = lane >> 2, tg = lane & 3;

    const int bm = blockIdx.y * GBM, bn = blockIdx.x * GBN;

    float acc[4][4][4];
#pragma unroll
    for (int i = 0; i < 4; i++)
#pragma unroll
        for (int j = 0; j < 4; j++)
#pragma unroll
            for (int r = 0; r < 4; r++) acc[i][j][r] = 0.0f;

    float4 aStage[4], bStage[4];

    // A loader: 128x32 floats = 1024 float4; idx -> row = idx>>3, c4 = (idx&7)*4
    // B loader: 32x128 floats = 1024 float4; idx -> krow = idx>>5, c4 = (idx&31)*4
    const float* Abase = A + (long)bm * K;
    const float* Wbase = W + bn;

#define LOAD_STAGE(k0)                                                          \
    {                                                                           \
        _Pragma("unroll") for (int i = 0; i < 4; i++) {                         \
            int idx = tid + 256 * i;                                            \
            aStage[i] = *(const float4*)(Abase + (long)(idx >> 3) * K + (k0) +  \
                                         (idx & 7) * 4);                        \
            bStage[i] = *(const float4*)(Wbase + (long)((k0) + (idx >> 5)) *    \
                                         Ncols + (idx & 31) * 4);               \
        }                                                                       \
    }

#define STORE_STAGE()                                                           \
    {                                                                           \
        _Pragma("unroll") for (int i = 0; i < 4; i++) {                         \
            int idx = tid + 256 * i;                                            \
            int ar = idx >> 3, ac = (idx & 7) * 4;                              \
            As[ar][ac + 0] = to_tf32(aStage[i].x);                              \
            As[ar][ac + 1] = to_tf32(aStage[i].y);                              \
            As[ar][ac + 2] = to_tf32(aStage[i].z);                              \
            As[ar][ac + 3] = to_tf32(aStage[i].w);                              \
            int br = idx >> 5, bc = (idx & 31) * 4;                             \
            Bs[br][bc + 0] = to_tf32(bStage[i].x);                              \
            Bs[br][bc + 1] = to_tf32(bStage[i].y);                              \
            Bs[br][bc + 2] = to_tf32(bStage[i].z);                              \
            Bs[br][bc + 3] = to_tf32(bStage[i].w);                              \
        }                                                                       \
    }

#define COMPUTE_CHUNK()                                                         \
    {                                                                           \
        _Pragma("unroll") for (int kk = 0; kk < 4; kk++) {                      \
            const int kb = kk * 8;                                              \
            float af[4][4];                                                     \
            _Pragma("unroll") for (int ma = 0; ma < 4; ma++) {                  \
                const int mr = wm + ma * 16 + gp;                               \
                af[ma][0] = As[mr][kb + tg];                                    \
                af[ma][1] = As[mr + 8][kb + tg];                                \
                af[ma][2] = As[mr][kb + tg + 4];                                \
                af[ma][3] = As[mr + 8][kb + tg + 4];                            \
            }                                                                   \
            float bf[4][2];                                                     \
            _Pragma("unroll") for (int nb = 0; nb < 4; nb++) {                  \
                const int nc = wn + nb * 8 + gp;                                \
                bf[nb][0] = Bs[kb + tg][nc];                                    \
                bf[nb][1] = Bs[kb + tg + 4][nc];                                \
            }                                                                   \
            _Pragma("unroll") for (int ma = 0; ma < 4; ma++)                    \
                _Pragma("unroll") for (int nb = 0; nb < 4; nb++)                \
                    mma_tf32(acc[ma][nb][0], acc[ma][nb][1], acc[ma][nb][2],    \
                             acc[ma][nb][3], af[ma][0], af[ma][1], af[ma][2],   \
                             af[ma][3], bf[nb][0], bf[nb][1]);                  \
        }                                                                       \
    }

    LOAD_STAGE(0);
    STORE_STAGE();
    __syncthreads();

    for (int k0 = GBK; k0 < K; k0 += GBK) {
        LOAD_STAGE(k0);      // prefetch next chunk into registers
        COMPUTE_CHUNK();     // compute current chunk from smem
        __syncthreads();
        STORE_STAGE();
        __syncthreads();
    }
    COMPUTE_CHUNK();

    // epilogue
#pragma unroll
    for (int ma = 0; ma < 4; ma++) {
        const long r0 = bm + wm + ma * 16 + gp;
        const long r1 = r0 + 8;
#pragma unroll
        for (int nb = 0; nb < 4; nb++) {
            const int col = bn + wn + nb * 8 + tg * 2;
            float2 v0 = make_float2(acc[ma][nb][0], acc[ma][nb][1]);
            float2 v1 = make_float2(acc[ma][nb][2], acc[ma][nb][3]);
            if (BIAS) {
                const float bb0 = __ldg(bias + col), bb1 = __ldg(bias + col + 1);
                v0.x += bb0; v0.y += bb1;
                v1.x += bb0; v1.y += bb1;
            }
            *(float2*)(C + r0 * Ncols + col) = v0;
            *(float2*)(C + r1 * Ncols + col) = v1;
        }
    }
#undef LOAD_STAGE
#undef STORE_STAGE
#undef COMPUTE_CHUNK
}

// ---------------- positional softmax: pos[h,n,:] = softmax(rel@W_pos+b) --------
__global__ __launch_bounds__(256) void pos_kernel(const float* __restrict__ rel,
                                                  const float* __restrict__ Wp,
                                                  const float* __restrict__ bp,
                                                  float* __restrict__ pos) {
    const int n = blockIdx.x, h = blockIdx.y, tid = threadIdx.x;
    __shared__ float red[8];
    __shared__ float bcv;
    const float w0 = Wp[h], w1 = Wp[HH + h], w2 = Wp[2 * HH + h], bb = bp[h];
    const float* r = rel + (long)n * NN * 3;

    float s0, s1, s2 = -1e30f;
    {
        const float* p = r + tid * 3;
        s0 = p[0] * w0 + p[1] * w1 + p[2] * w2 + bb;
        p = r + (tid + 256) * 3;
        s1 = p[0] * w0 + p[1] * w1 + p[2] * w2 + bb;
        if (tid < 64) {
            p = r + (tid + 512) * 3;
            s2 = p[0] * w0 + p[1] * w1 + p[2] * w2 + bb;
        }
    }
    float mx = fmaxf(fmaxf(s0, s1), s2);
#pragma unroll
    for (int o = 16; o; o >>= 1) mx = fmaxf(mx, __shfl_xor_sync(~0u, mx, o));
    if ((tid & 31) == 0) red[tid >> 5] = mx;
    __syncthreads();
    if (tid == 0) {
        float m = red[0];
        for (int i = 1; i < 8; i++) m = fmaxf(m, red[i]);
        bcv = m;
    }
    __syncthreads();
    mx = bcv;
    float e0 = expf(s0 - mx), e1 = expf(s1 - mx);
    float e2 = (tid < 64) ? expf(s2 - mx) : 0.0f;
    float sum = e0 + e1 + e2;
#pragma unroll
    for (int o = 16; o; o >>= 1) sum += __shfl_xor_sync(~0u, sum, o);
    __syncthreads();
    if ((tid & 31) == 0) red[tid >> 5] = sum;
    __syncthreads();
    if (tid == 0) {
        float s = 0.f;
        for (int i = 0; i < 8; i++) s += red[i];
        bcv = 1.0f / s;
    }
    __syncthreads();
    const float inv = bcv;
    float* out = pos + ((long)h * NN + n) * NN;
    out[tid] = e0 * inv;
    out[tid + 256] = e1 * inv;
    if (tid < 64) out[tid + 512] = e2 * inv;
}

// ---------------- scores: S[b,h] = q @ k^T * scale -----------------------------
__global__ __launch_bounds__(256) void score_kernel(const float* __restrict__ qk,
                                                    float* __restrict__ attn) {
    const int bh = blockIdx.z;
    const int b = bh >> 4, h = bh & 15;
    const int n0 = blockIdx.y * 64, m0 = blockIdx.x * 64;
    __shared__ float qs[64][65];
    __shared__ float ks[64][65];
    const int tid = threadIdx.x, tx = tid & 15, ty = tid >> 4;

    const float* qbase = qk + (long)b * NN * 2048 + h * 64;
    const float* kbase = qbase + 1024;
    for (int idx = tid; idx < 64 * 16; idx += 256) {
        const int r = idx >> 4, c4 = (idx & 15) * 4;
        float4 a = *(const float4*)(qbase + (long)(n0 + r) * 2048 + c4);
        qs[r][c4] = a.x; qs[r][c4 + 1] = a.y; qs[r][c4 + 2] = a.z; qs[r][c4 + 3] = a.w;
        float4 c = *(const float4*)(kbase + (long)(m0 + r) * 2048 + c4);
        ks[r][c4] = c.x; ks[r][c4 + 1] = c.y; ks[r][c4 + 2] = c.z; ks[r][c4 + 3] = c.w;
    }
    __syncthreads();

    float acc[4][4];
#pragma unroll
    for (int i = 0; i < 4; i++)
#pragma unroll
        for (int j = 0; j < 4; j++) acc[i][j] = 0.0f;

#pragma unroll 8
    for (int d = 0; d < 64; d++) {
        float a[4], bf[4];
#pragma unroll
        for (int i = 0; i < 4; i++) a[i] = qs[ty + 16 * i][d];
#pragma unroll
        for (int j = 0; j < 4; j++) bf[j] = ks[tx + 16 * j][d];
#pragma unroll
        for (int i = 0; i < 4; i++)
#pragma unroll
            for (int j = 0; j < 4; j++) acc[i][j] += a[i] * bf[j];
    }

    const float scale = 0.125f;
#pragma unroll
    for (int i = 0; i < 4; i++) {
        float* dst = attn + ((long)bh * NN + n0 + ty + 16 * i) * NN + m0;
#pragma unroll
        for (int j = 0; j < 4; j++) dst[tx + 16 * j] = acc[i][j] * scale;
    }
}

// ---------------- softmax + gated mix + renorm (in place on g_attn) ------------
__global__ __launch_bounds__(256) void mix_kernel(const float* __restrict__ pos,
                                                  const float* __restrict__ gating,
                                                  float* __restrict__ attn) {
    const int n = blockIdx.x;
    const int bh = blockIdx.y;
    const int h = bh & 15;
    const int tid = threadIdx.x;
    __shared__ float red[8];
    __shared__ float bcv;

    float* arow = attn + ((long)bh * NN + n) * NN;
    const float* prow = pos + ((long)h * NN + n) * NN;
    const float g = 1.0f / (1.0f + expf(-gating[h]));

    float s0 = arow[tid];
    float s1 = arow[tid + 256];
    float s2 = (tid < 64) ? arow[tid + 512] : -1e30f;

    float mx = fmaxf(fmaxf(s0, s1), s2);
#pragma unroll
    for (int o = 16; o; o >>= 1) mx = fmaxf(mx, __shfl_xor_sync(~0u, mx, o));
    if ((tid & 31) == 0) red[tid >> 5] = mx;
    __syncthreads();
    if (tid == 0) {
        float m = red[0];
        for (int i = 1; i < 8; i++) m = fmaxf(m, red[i]);
        bcv = m;
    }
    __syncthreads();
    mx = bcv;

    float e0 = expf(s0 - mx), e1 = expf(s1 - mx);
    float e2 = (tid < 64) ? expf(s2 - mx) : 0.0f;
    float sum = e0 + e1 + e2;
#pragma unroll
    for (int o = 16; o; o >>= 1) sum += __shfl_xor_sync(~0u, sum, o);
    __syncthreads();
    if ((tid & 31) == 0) red[tid >> 5] = sum;
    __syncthreads();
    if (tid == 0) {
        float s = 0.f;
        for (int i = 0; i < 8; i++) s += red[i];
        bcv = 1.0f / s;
    }
    __syncthreads();
    const float inv = bcv;

    const float og = 1.0f - g;
    float a0 = og * e0 * inv + g * prow[tid];
    float a1 = og * e1 * inv + g * prow[tid + 256];
    float a2 = (tid < 64) ? (og * e2 * inv + g * prow[tid + 512]) : 0.0f;

    float tot = a0 + a1 + a2;
#pragma unroll
    for (int o = 16; o; o >>= 1) tot += __shfl_xor_sync(~0u, tot, o);
    __syncthreads();
    if ((tid & 31) == 0) red[tid >> 5] = tot;
    __syncthreads();
    if (tid == 0) {
        float s = 0.f;
        for (int i = 0; i < 8; i++) s += red[i];
        bcv = 1.0f / s;
    }
    __syncthreads();
    const float inv2 = bcv;

    arow[tid] = a0 * inv2;
    arow[tid + 256] = a1 * inv2;
    if (tid < 64) arow[tid + 512] = a2 * inv2;
}

// ---------------- O[b,h] = attn[b,h] @ v[b,h] ----------------------------------
__global__ __launch_bounds__(256) void av_kernel(const float* __restrict__ attn,
                                                 const float* __restrict__ v,
                                                 float* __restrict__ o) {
    const int bh = blockIdx.y;
    const int b = bh >> 4, h = bh & 15;
    const int n0 = blockIdx.x * 64;
    __shared__ float as[64][65];
    __shared__ float vs[64][64];
    const int tid = threadIdx.x, tx = tid & 15, ty = tid >> 4;

    float acc[4][4];
#pragma unroll
    for (int i = 0; i < 4; i++)
#pragma unroll
        for (int j = 0; j < 4; j++) acc[i][j] = 0.0f;

    for (int m0 = 0; m0 < NN; m0 += 64) {
        for (int idx = tid; idx < 64 * 16; idx += 256) {
            const int r = idx >> 4, c4 = (idx & 15) * 4;
            float4 a = *(const float4*)(attn + ((long)bh * NN + n0 + r) * NN + m0 + c4);
            as[r][c4] = a.x; as[r][c4 + 1] = a.y; as[r][c4 + 2] = a.z; as[r][c4 + 3] = a.w;
            *(float4*)(&vs[r][c4]) =
                *(const float4*)(v + ((long)(b * NN + m0 + r)) * DD + h * 64 + c4);
        }
        __syncthreads();
#pragma unroll 8
        for (int mm = 0; mm < 64; mm++) {
            float a[4], bf[4];
#pragma unroll
            for (int i = 0; i < 4; i++) a[i] = as[ty + 16 * i][mm];
#pragma unroll
            for (int j = 0; j < 4; j++) bf[j] = vs[mm][tx + 16 * j];
#pragma unroll
            for (int i = 0; i < 4; i++)
#pragma unroll
                for (int j = 0; j < 4; j++) acc[i][j] += a[i] * bf[j];
        }
        __syncthreads();
    }

#pragma unroll
    for (int i = 0; i < 4; i++) {
        float* dst = o + ((long)(b * NN + n0 + ty + 16 * i)) * DD + h * 64;
#pragma unroll
        for (int j = 0; j < 4; j++) dst[tx + 16 * j] = acc[i][j];
    }
}

// ---------------- launch ----------------
extern "C" void kernel_launch(void* const* d_in, const int* in_sizes, int n_in,
                              void* d_out, int out_size) {
    const float* x      = (const float*)d_in[0];  // [B,N,D]
    const float* W_qk   = (const float*)d_in[1];  // [D,2D]
    const float* W_v    = (const float*)d_in[2];  // [D,D]
    const float* W_proj = (const float*)d_in[3];  // [D,D]
    const float* b_proj = (const float*)d_in[4];  // [D]
    const float* W_pos  = (const float*)d_in[5];  // [3,H]
    const float* b_pos  = (const float*)d_in[6];  // [H]
    const float* gating = (const float*)d_in[7];  // [H]
    const float* rel    = (const float*)d_in[8];  // [N,N,3]
    float* out = (float*)d_out;

    float* qk;   cudaGetSymbolAddress((void**)&qk,   g_qk);
    float* vbuf; cudaGetSymbolAddress((void**)&vbuf, g_v);
    float* pos;  cudaGetSymbolAddress((void**)&pos,  g_pos);
    float* attn; cudaGetSymbolAddress((void**)&attn, g_attn);
    float* obuf; cudaGetSymbolAddress((void**)&obuf, g_o);

    const int M = BB * NN;  // 9216

    // 1) qk = x @ W_qk   [9216,1024]x[1024,2048]  (tf32 tensor cores)
    gemm_tf32<false><<<dim3(2 * DD / 128, M / 128), 256>>>(x, W_qk, nullptr, qk, M, DD, 2 * DD);
    // 2) v = x @ W_v
    gemm_tf32<false><<<dim3(DD / 128, M / 128), 256>>>(x, W_v, nullptr, vbuf, M, DD, DD);
    // 3) positional softmax
    pos_kernel<<<dim3(NN, HH), 256>>>(rel, W_pos, b_pos, pos);
    // 4) scores
    score_kernel<<<dim3(NN / 64, NN / 64, BB * HH), 256>>>(qk, attn);
    // 5) softmax + gated mix + renorm
    mix_kernel<<<dim3(NN, BB * HH), 256>>>(pos, gating, attn);
    // 6) attn @ v
    av_kernel<<<dim3(NN / 64, BB * HH), 256>>>(attn, vbuf, obuf);
    // 7) out = o @ W_proj + b_proj  (tf32 tensor cores)
    gemm_tf32<true><<<dim3(DD / 128, M / 128), 256>>>(obuf, W_proj, b_proj, out, M, DD, DD);
}

// round 4
// speedup vs baseline: 2.3666x; 1.2278x over previous
#include <cuda_runtime.h>
#include <cuda_bf16.h>
#include <cstdint>

#define BB 16
#define NN 576
#define DD 1024
#define HH 16
#define HD 64

// ---------------- scratch (static device globals; no allocation) ----------------
__device__ float g_qk[(long)BB * NN * 2 * DD];        // [B,N,2D]  75.5 MB
__device__ float g_v[(long)BB * NN * DD];             // [B,N,D]   37.7 MB
__device__ float g_pos[(long)HH * NN * NN];           // [H,N,N]   21 MB
__device__ float g_o[(long)BB * NN * DD];             // [B,N,D]   37.7 MB

// ---------------- tf32 helpers -------------------------------------------------
__device__ __forceinline__ float to_tf32(float x) {
    unsigned r;
    asm("cvt.rna.tf32.f32 %0, %1;" : "=r"(r) : "f"(x));
    return __uint_as_float(r);
}

__device__ __forceinline__ void mma_tf32(float& d0, float& d1, float& d2, float& d3,
                                         float a0, float a1, float a2, float a3,
                                         float b0, float b1) {
    asm volatile(
        "mma.sync.aligned.m16n8k8.row.col.f32.tf32.tf32.f32 "
        "{%0,%1,%2,%3}, {%4,%5,%6,%7}, {%8,%9}, {%0,%1,%2,%3};\n"
        : "+f"(d0), "+f"(d1), "+f"(d2), "+f"(d3)
        : "r"(__float_as_uint(a0)), "r"(__float_as_uint(a1)),
          "r"(__float_as_uint(a2)), "r"(__float_as_uint(a3)),
          "r"(__float_as_uint(b0)), "r"(__float_as_uint(b1)));
}

// ---------------- tf32 tensor-core GEMM: C = A[M,K] @ W[K,Nc] (+bias) ----------
#define GBM 128
#define GBN 128
#define GBK 32

template <bool BIAS>
__global__ __launch_bounds__(256, 2) void gemm_tf32(const float* __restrict__ A,
                                                    const float* __restrict__ W,
                                                    const float* __restrict__ bias,
                                                    float* __restrict__ C,
                                                    int M, int K, int Ncols) {
    __shared__ float As[GBM][GBK + 4];
    __shared__ float Bs[GBK][GBN + 8];

    const int tid = threadIdx.x;
    const int warp = tid >> 5, lane = tid & 31;
    const int wm = (warp & 1) * 64;
    const int wn = (warp >> 1) * 32;
    const int gp = lane >> 2, tg = lane & 3;

    const int bm = blockIdx.y * GBM, bn = blockIdx.x * GBN;

    float acc[4][4][4];
#pragma unroll
    for (int i = 0; i < 4; i++)
#pragma unroll
        for (int j = 0; j < 4; j++)
#pragma unroll
            for (int r = 0; r < 4; r++) acc[i][j][r] = 0.0f;

    float4 aStage[4], bStage[4];
    const float* Abase = A + (long)bm * K;
    const float* Wbase = W + bn;

#define LOAD_STAGE(k0)                                                          \
    {                                                                           \
        _Pragma("unroll") for (int i = 0; i < 4; i++) {                         \
            int idx = tid + 256 * i;                                            \
            aStage[i] = *(const float4*)(Abase + (long)(idx >> 3) * K + (k0) +  \
                                         (idx & 7) * 4);                        \
            bStage[i] = *(const float4*)(Wbase + (long)((k0) + (idx >> 5)) *    \
                                         Ncols + (idx & 31) * 4);               \
        }                                                                       \
    }

#define STORE_STAGE()                                                           \
    {                                                                           \
        _Pragma("unroll") for (int i = 0; i < 4; i++) {                         \
            int idx = tid + 256 * i;                                            \
            int ar = idx >> 3, ac = (idx & 7) * 4;                              \
            As[ar][ac + 0] = to_tf32(aStage[i].x);                              \
            As[ar][ac + 1] = to_tf32(aStage[i].y);                              \
            As[ar][ac + 2] = to_tf32(aStage[i].z);                              \
            As[ar][ac + 3] = to_tf32(aStage[i].w);                              \
            int br = idx >> 5, bc = (idx & 31) * 4;                             \
            Bs[br][bc + 0] = to_tf32(bStage[i].x);                              \
            Bs[br][bc + 1] = to_tf32(bStage[i].y);                              \
            Bs[br][bc + 2] = to_tf32(bStage[i].z);                              \
            Bs[br][bc + 3] = to_tf32(bStage[i].w);                              \
        }                                                                       \
    }

#define COMPUTE_CHUNK()                                                         \
    {                                                                           \
        _Pragma("unroll") for (int kk = 0; kk < 4; kk++) {                      \
            const int kb = kk * 8;                                              \
            float af[4][4];                                                     \
            _Pragma("unroll") for (int ma = 0; ma < 4; ma++) {                  \
                const int mr = wm + ma * 16 + gp;                               \
                af[ma][0] = As[mr][kb + tg];                                    \
                af[ma][1] = As[mr + 8][kb + tg];                                \
                af[ma][2] = As[mr][kb + tg + 4];                                \
                af[ma][3] = As[mr + 8][kb + tg + 4];                            \
            }                                                                   \
            float bf[4][2];                                                     \
            _Pragma("unroll") for (int nb = 0; nb < 4; nb++) {                  \
                const int nc = wn + nb * 8 + gp;                                \
                bf[nb][0] = Bs[kb + tg][nc];                                    \
                bf[nb][1] = Bs[kb + tg + 4][nc];                                \
            }                                                                   \
            _Pragma("unroll") for (int ma = 0; ma < 4; ma++)                    \
                _Pragma("unroll") for (int nb = 0; nb < 4; nb++)                \
                    mma_tf32(acc[ma][nb][0], acc[ma][nb][1], acc[ma][nb][2],    \
                             acc[ma][nb][3], af[ma][0], af[ma][1], af[ma][2],   \
                             af[ma][3], bf[nb][0], bf[nb][1]);                  \
        }                                                                       \
    }

    LOAD_STAGE(0);
    STORE_STAGE();
    __syncthreads();

    for (int k0 = GBK; k0 < K; k0 += GBK) {
        LOAD_STAGE(k0);
        COMPUTE_CHUNK();
        __syncthreads();
        STORE_STAGE();
        __syncthreads();
    }
    COMPUTE_CHUNK();

#pragma unroll
    for (int ma = 0; ma < 4; ma++) {
        const long r0 = bm + wm + ma * 16 + gp;
        const long r1 = r0 + 8;
#pragma unroll
        for (int nb = 0; nb < 4; nb++) {
            const int col = bn + wn + nb * 8 + tg * 2;
            float2 v0 = make_float2(acc[ma][nb][0], acc[ma][nb][1]);
            float2 v1 = make_float2(acc[ma][nb][2], acc[ma][nb][3]);
            if (BIAS) {
                const float bb0 = __ldg(bias + col), bb1 = __ldg(bias + col + 1);
                v0.x += bb0; v0.y += bb1;
                v1.x += bb0; v1.y += bb1;
            }
            *(float2*)(C + r0 * Ncols + col) = v0;
            *(float2*)(C + r1 * Ncols + col) = v1;
        }
    }
#undef LOAD_STAGE
#undef STORE_STAGE
#undef COMPUTE_CHUNK
}

// ---------------- positional softmax: pos[h,n,:] = softmax(rel@W_pos+b) --------
__global__ __launch_bounds__(256) void pos_kernel(const float* __restrict__ rel,
                                                  const float* __restrict__ Wp,
                                                  const float* __restrict__ bp,
                                                  float* __restrict__ pos) {
    const int n = blockIdx.x, h = blockIdx.y, tid = threadIdx.x;
    __shared__ float red[8];
    __shared__ float bcv;
    const float w0 = Wp[h], w1 = Wp[HH + h], w2 = Wp[2 * HH + h], bb = bp[h];
    const float* r = rel + (long)n * NN * 3;

    float s0, s1, s2 = -1e30f;
    {
        const float* p = r + tid * 3;
        s0 = p[0] * w0 + p[1] * w1 + p[2] * w2 + bb;
        p = r + (tid + 256) * 3;
        s1 = p[0] * w0 + p[1] * w1 + p[2] * w2 + bb;
        if (tid < 64) {
            p = r + (tid + 512) * 3;
            s2 = p[0] * w0 + p[1] * w1 + p[2] * w2 + bb;
        }
    }
    float mx = fmaxf(fmaxf(s0, s1), s2);
#pragma unroll
    for (int o = 16; o; o >>= 1) mx = fmaxf(mx, __shfl_xor_sync(~0u, mx, o));
    if ((tid & 31) == 0) red[tid >> 5] = mx;
    __syncthreads();
    if (tid == 0) {
        float m = red[0];
        for (int i = 1; i < 8; i++) m = fmaxf(m, red[i]);
        bcv = m;
    }
    __syncthreads();
    mx = bcv;
    float e0 = expf(s0 - mx), e1 = expf(s1 - mx);
    float e2 = (tid < 64) ? expf(s2 - mx) : 0.0f;
    float sum = e0 + e1 + e2;
#pragma unroll
    for (int o = 16; o; o >>= 1) sum += __shfl_xor_sync(~0u, sum, o);
    __syncthreads();
    if ((tid & 31) == 0) red[tid >> 5] = sum;
    __syncthreads();
    if (tid == 0) {
        float s = 0.f;
        for (int i = 0; i < 8; i++) s += red[i];
        bcv = 1.0f / s;
    }
    __syncthreads();
    const float inv = bcv;
    float* out = pos + ((long)h * NN + n) * NN;
    out[tid] = e0 * inv;
    out[tid + 256] = e1 * inv;
    if (tid < 64) out[tid + 512] = e2 * inv;
}

// ---------------- fused attention ----------------------------------------------
// One block = (b, h, 64 q-rows). Phase 1: S = q@k^T (split-tf32, full 576 cols
// into smem). Phase 2: row softmax + gated mix with pos (attn sums to 1 -> no
// renorm needed). Phase 3: out = P @ v (tf32 mma).
// Dynamic smem: Sbuf[64][580] + qs_hi/qs_lo/kv_hi/kv_lo [64][68] = 218112 B.
#define FA_SMEM 218112

__global__ __launch_bounds__(256, 1) void fused_attn(
    const float* __restrict__ qk, const float* __restrict__ v,
    const float* __restrict__ pos, const float* __restrict__ gating,
    float* __restrict__ o) {
    extern __shared__ float smem[];
    float* Sbuf  = smem;                 // [64][580]
    float* qs_hi = smem + 64 * 580;      // [64][68]
    float* qs_lo = qs_hi + 64 * 68;
    float* kv_hi = qs_lo + 64 * 68;
    float* kv_lo = kv_hi + 64 * 68;

    const int tid = threadIdx.x, warp = tid >> 5, lane = tid & 31;
    const int gp = lane >> 2, tg = lane & 3;
    const int n0 = blockIdx.x * 64;
    const int b = blockIdx.y >> 4, h = blockIdx.y & 15;
    const int wm = (warp & 1) * 32, wn = (warp >> 1) * 16;

    const float* qbase = qk + (long)b * NN * 2048 + h * 64;
    const float* kbase = qbase + 1024;

    // ---- load q tile (hi/lo split) ----
    {
        int idx = tid;
#pragma unroll
        for (int i = 0; i < 4; i++, idx += 256) {
            int r = idx >> 4, c4 = (idx & 15) * 4;
            float4 a = *(const float4*)(qbase + (long)(n0 + r) * 2048 + c4);
            float h0 = to_tf32(a.x), h1 = to_tf32(a.y), h2 = to_tf32(a.z), h3 = to_tf32(a.w);
            qs_hi[r * 68 + c4 + 0] = h0; qs_lo[r * 68 + c4 + 0] = to_tf32(a.x - h0);
            qs_hi[r * 68 + c4 + 1] = h1; qs_lo[r * 68 + c4 + 1] = to_tf32(a.y - h1);
            qs_hi[r * 68 + c4 + 2] = h2; qs_lo[r * 68 + c4 + 2] = to_tf32(a.z - h2);
            qs_hi[r * 68 + c4 + 3] = h3; qs_lo[r * 68 + c4 + 3] = to_tf32(a.w - h3);
        }
    }

    // ---- phase 1: S strip ----
    const float scale = 0.125f;
    for (int m0 = 0; m0 < NN; m0 += 64) {
        __syncthreads();  // kv reuse (and q visibility on first iter)
        {
            int idx = tid;
#pragma unroll
            for (int i = 0; i < 4; i++, idx += 256) {
                int r = idx >> 4, c4 = (idx & 15) * 4;
                float4 a = *(const float4*)(kbase + (long)(m0 + r) * 2048 + c4);
                float h0 = to_tf32(a.x), h1 = to_tf32(a.y), h2 = to_tf32(a.z), h3 = to_tf32(a.w);
                kv_hi[(c4 + 0) * 68 + r] = h0; kv_lo[(c4 + 0) * 68 + r] = to_tf32(a.x - h0);
                kv_hi[(c4 + 1) * 68 + r] = h1; kv_lo[(c4 + 1) * 68 + r] = to_tf32(a.y - h1);
                kv_hi[(c4 + 2) * 68 + r] = h2; kv_lo[(c4 + 2) * 68 + r] = to_tf32(a.z - h2);
                kv_hi[(c4 + 3) * 68 + r] = h3; kv_lo[(c4 + 3) * 68 + r] = to_tf32(a.w - h3);
            }
        }
        __syncthreads();

        float acc[2][2][4];
#pragma unroll
        for (int i = 0; i < 2; i++)
#pragma unroll
            for (int j = 0; j < 2; j++)
#pragma unroll
                for (int r = 0; r < 4; r++) acc[i][j][r] = 0.0f;

#pragma unroll
        for (int kk = 0; kk < 8; kk++) {
            const int kb = kk * 8;
            float ah[2][4], al[2][4];
#pragma unroll
            for (int ma = 0; ma < 2; ma++) {
                const int mr = wm + ma * 16 + gp;
                ah[ma][0] = qs_hi[mr * 68 + kb + tg];       al[ma][0] = qs_lo[mr * 68 + kb + tg];
                ah[ma][1] = qs_hi[(mr + 8) * 68 + kb + tg]; al[ma][1] = qs_lo[(mr + 8) * 68 + kb + tg];
                ah[ma][2] = qs_hi[mr * 68 + kb + tg + 4];   al[ma][2] = qs_lo[mr * 68 + kb + tg + 4];
                ah[ma][3] = qs_hi[(mr + 8) * 68 + kb + tg + 4]; al[ma][3] = qs_lo[(mr + 8) * 68 + kb + tg + 4];
            }
            float bh[2][2], bl[2][2];
#pragma unroll
            for (int nb = 0; nb < 2; nb++) {
                const int nc = wn + nb * 8 + gp;
                bh[nb][0] = kv_hi[(kb + tg) * 68 + nc]; bh[nb][1] = kv_hi[(kb + tg + 4) * 68 + nc];
                bl[nb][0] = kv_lo[(kb + tg) * 68 + nc]; bl[nb][1] = kv_lo[(kb + tg + 4) * 68 + nc];
            }
#pragma unroll
            for (int ma = 0; ma < 2; ma++)
#pragma unroll
                for (int nb = 0; nb < 2; nb++) {
                    mma_tf32(acc[ma][nb][0], acc[ma][nb][1], acc[ma][nb][2], acc[ma][nb][3],
                             ah[ma][0], ah[ma][1], ah[ma][2], ah[ma][3], bh[nb][0], bh[nb][1]);
                    mma_tf32(acc[ma][nb][0], acc[ma][nb][1], acc[ma][nb][2], acc[ma][nb][3],
                             ah[ma][0], ah[ma][1], ah[ma][2], ah[ma][3], bl[nb][0], bl[nb][1]);
                    mma_tf32(acc[ma][nb][0], acc[ma][nb][1], acc[ma][nb][2], acc[ma][nb][3],
                             al[ma][0], al[ma][1], al[ma][2], al[ma][3], bh[nb][0], bh[nb][1]);
                }
        }
#pragma unroll
        for (int ma = 0; ma < 2; ma++) {
            const int r0 = wm + ma * 16 + gp;
#pragma unroll
            for (int nb = 0; nb < 2; nb++) {
                const int col = m0 + wn + nb * 8 + tg * 2;
                Sbuf[r0 * 580 + col]           = acc[ma][nb][0] * scale;
                Sbuf[r0 * 580 + col + 1]       = acc[ma][nb][1] * scale;
                Sbuf[(r0 + 8) * 580 + col]     = acc[ma][nb][2] * scale;
                Sbuf[(r0 + 8) * 580 + col + 1] = acc[ma][nb][3] * scale;
            }
        }
    }
    __syncthreads();

    // ---- phase 2: softmax + gated mix (warp w handles rows w*8..w*8+7) ----
    const float g = 1.0f / (1.0f + __expf(-gating[h]));
    const float og = 1.0f - g;
    const float* pbase = pos + ((long)h * NN + n0) * NN;
    for (int r = 0; r < 8; r++) {
        const int row = warp * 8 + r;
        float* srow = Sbuf + row * 580;
        float vals[18];
        float mx = -1e30f;
#pragma unroll
        for (int i = 0; i < 18; i++) {
            vals[i] = srow[lane + 32 * i];
            mx = fmaxf(mx, vals[i]);
        }
#pragma unroll
        for (int ofs = 16; ofs; ofs >>= 1) mx = fmaxf(mx, __shfl_xor_sync(~0u, mx, ofs));
        float s = 0.0f;
#pragma unroll
        for (int i = 0; i < 18; i++) {
            vals[i] = __expf(vals[i] - mx);
            s += vals[i];
        }
#pragma unroll
        for (int ofs = 16; ofs; ofs >>= 1) s += __shfl_xor_sync(~0u, s, ofs);
        const float coef = og / s;
        const float* prow = pbase + (long)row * NN;
#pragma unroll
        for (int i = 0; i < 18; i++)
            srow[lane + 32 * i] = to_tf32(vals[i] * coef + g * prow[lane + 32 * i]);
    }

    // ---- phase 3: out = P @ v ----
    float acc2[2][2][4];
#pragma unroll
    for (int i = 0; i < 2; i++)
#pragma unroll
        for (int j = 0; j < 2; j++)
#pragma unroll
            for (int r = 0; r < 4; r++) acc2[i][j][r] = 0.0f;

    const float* vbase = v + (long)b * NN * DD + h * 64;
    for (int m0 = 0; m0 < NN; m0 += 64) {
        __syncthreads();
        {
            int idx = tid;
#pragma unroll
            for (int i = 0; i < 4; i++, idx += 256) {
                int r = idx >> 4, c4 = (idx & 15) * 4;
                float4 a = *(const float4*)(vbase + (long)(m0 + r) * DD + c4);
                float4 t = make_float4(to_tf32(a.x), to_tf32(a.y), to_tf32(a.z), to_tf32(a.w));
                *(float4*)(kv_hi + r * 68 + c4) = t;
            }
        }
        __syncthreads();
#pragma unroll
        for (int kk = 0; kk < 8; kk++) {
            const int kb = kk * 8;
            float af[2][4];
#pragma unroll
            for (int ma = 0; ma < 2; ma++) {
                const int mr = wm + ma * 16 + gp;
                af[ma][0] = Sbuf[mr * 580 + m0 + kb + tg];
                af[ma][1] = Sbuf[(mr + 8) * 580 + m0 + kb + tg];
                af[ma][2] = Sbuf[mr * 580 + m0 + kb + tg + 4];
                af[ma][3] = Sbuf[(mr + 8) * 580 + m0 + kb + tg + 4];
            }
            float bf2[2][2];
#pragma unroll
            for (int nb = 0; nb < 2; nb++) {
                const int nc = wn + nb * 8 + gp;
                bf2[nb][0] = kv_hi[(kb + tg) * 68 + nc];
                bf2[nb][1] = kv_hi[(kb + tg + 4) * 68 + nc];
            }
#pragma unroll
            for (int ma = 0; ma < 2; ma++)
#pragma unroll
                for (int nb = 0; nb < 2; nb++)
                    mma_tf32(acc2[ma][nb][0], acc2[ma][nb][1], acc2[ma][nb][2], acc2[ma][nb][3],
                             af[ma][0], af[ma][1], af[ma][2], af[ma][3], bf2[nb][0], bf2[nb][1]);
        }
    }

    // ---- epilogue ----
#pragma unroll
    for (int ma = 0; ma < 2; ma++) {
        const long row = n0 + wm + ma * 16 + gp;
#pragma unroll
        for (int nb = 0; nb < 2; nb++) {
            const int col = h * 64 + wn + nb * 8 + tg * 2;
            float* dst = o + ((long)b * NN + row) * DD + col;
            *(float2*)dst = make_float2(acc2[ma][nb][0], acc2[ma][nb][1]);
            *(float2*)(dst + 8L * DD) = make_float2(acc2[ma][nb][2], acc2[ma][nb][3]);
        }
    }
}

// ---------------- launch ----------------
extern "C" void kernel_launch(void* const* d_in, const int* in_sizes, int n_in,
                              void* d_out, int out_size) {
    const float* x      = (const float*)d_in[0];
    const float* W_qk   = (const float*)d_in[1];
    const float* W_v    = (const float*)d_in[2];
    const float* W_proj = (const float*)d_in[3];
    const float* b_proj = (const float*)d_in[4];
    const float* W_pos  = (const float*)d_in[5];
    const float* b_pos  = (const float*)d_in[6];
    const float* gating = (const float*)d_in[7];
    const float* rel    = (const float*)d_in[8];
    float* out = (float*)d_out;

    float* qk;   cudaGetSymbolAddress((void**)&qk,   g_qk);
    float* vbuf; cudaGetSymbolAddress((void**)&vbuf, g_v);
    float* pos;  cudaGetSymbolAddress((void**)&pos,  g_pos);
    float* obuf; cudaGetSymbolAddress((void**)&obuf, g_o);

    cudaFuncSetAttribute(fused_attn, cudaFuncAttributeMaxDynamicSharedMemorySize, FA_SMEM);

    const int M = BB * NN;  // 9216

    // 1) qk = x @ W_qk
    gemm_tf32<false><<<dim3(2 * DD / 128, M / 128), 256>>>(x, W_qk, nullptr, qk, M, DD, 2 * DD);
    // 2) v = x @ W_v
    gemm_tf32<false><<<dim3(DD / 128, M / 128), 256>>>(x, W_v, nullptr, vbuf, M, DD, DD);
    // 3) positional softmax
    pos_kernel<<<dim3(NN, HH), 256>>>(rel, W_pos, b_pos, pos);
    // 4) fused: scores + softmax + gated mix + @v   (no 340MB attn tensor)
    fused_attn<<<dim3(NN / 64, BB * HH), 256, FA_SMEM>>>(qk, vbuf, pos, gating, obuf);
    // 5) out = o @ W_proj + b_proj
    gemm_tf32<true><<<dim3(DD / 128, M / 128), 256>>>(obuf, W_proj, b_proj, out, M, DD, DD);
}

// round 5
// speedup vs baseline: 2.4992x; 1.0560x over previous
#include <cuda_runtime.h>
#include <cuda_bf16.h>
#include <cstdint>

#define BB 16
#define NN 576
#define DD 1024
#define HH 16
#define HD 64

// ---------------- scratch (static device globals; no allocation) ----------------
__device__ float g_qk[(long)BB * NN * 2 * DD];        // [B,N,2D]
__device__ float g_v[(long)BB * NN * DD];             // [B,N,D]
__device__ float g_pos[(long)HH * NN * NN];           // [H,N,N]
__device__ float g_o[(long)BB * NN * DD];             // [B,N,D]

// ---------------- tf32 helpers -------------------------------------------------
__device__ __forceinline__ float to_tf32(float x) {
    unsigned r;
    asm("cvt.rna.tf32.f32 %0, %1;" : "=r"(r) : "f"(x));
    return __uint_as_float(r);
}

__device__ __forceinline__ void mma_tf32(float& d0, float& d1, float& d2, float& d3,
                                         float a0, float a1, float a2, float a3,
                                         float b0, float b1) {
    asm volatile(
        "mma.sync.aligned.m16n8k8.row.col.f32.tf32.tf32.f32 "
        "{%0,%1,%2,%3}, {%4,%5,%6,%7}, {%8,%9}, {%0,%1,%2,%3};\n"
        : "+f"(d0), "+f"(d1), "+f"(d2), "+f"(d3)
        : "r"(__float_as_uint(a0)), "r"(__float_as_uint(a1)),
          "r"(__float_as_uint(a2)), "r"(__float_as_uint(a3)),
          "r"(__float_as_uint(b0)), "r"(__float_as_uint(b1)));
}

// ---------------- tf32 tensor-core GEMM: C = A[M,K] @ W[K,Nc] (+bias) ----------
#define GBM 128
#define GBN 128
#define GBK 32

template <bool BIAS>
__global__ __launch_bounds__(256, 2) void gemm_tf32(const float* __restrict__ A,
                                                    const float* __restrict__ W,
                                                    const float* __restrict__ bias,
                                                    float* __restrict__ C,
                                                    int M, int K, int Ncols) {
    __shared__ float As[GBM][GBK + 4];
    __shared__ float Bs[GBK][GBN + 8];

    const int tid = threadIdx.x;
    const int warp = tid >> 5, lane = tid & 31;
    const int wm = (warp & 1) * 64;
    const int wn = (warp >> 1) * 32;
    const int gp = lane >> 2, tg = lane & 3;

    const int bm = blockIdx.y * GBM, bn = blockIdx.x * GBN;

    float acc[4][4][4];
#pragma unroll
    for (int i = 0; i < 4; i++)
#pragma unroll
        for (int j = 0; j < 4; j++)
#pragma unroll
            for (int r = 0; r < 4; r++) acc[i][j][r] = 0.0f;

    float4 aStage[4], bStage[4];
    const float* Abase = A + (long)bm * K;
    const float* Wbase = W + bn;

#define LOAD_STAGE(k0)                                                          \
    {                                                                           \
        _Pragma("unroll") for (int i = 0; i < 4; i++) {                         \
            int idx = tid + 256 * i;                                            \
            aStage[i] = *(const float4*)(Abase + (long)(idx >> 3) * K + (k0) +  \
                                         (idx & 7) * 4);                        \
            bStage[i] = *(const float4*)(Wbase + (long)((k0) + (idx >> 5)) *    \
                                         Ncols + (idx & 31) * 4);               \
        }                                                                       \
    }

#define STORE_STAGE()                                                           \
    {                                                                           \
        _Pragma("unroll") for (int i = 0; i < 4; i++) {                         \
            int idx = tid + 256 * i;                                            \
            int ar = idx >> 3, ac = (idx & 7) * 4;                              \
            As[ar][ac + 0] = to_tf32(aStage[i].x);                              \
            As[ar][ac + 1] = to_tf32(aStage[i].y);                              \
            As[ar][ac + 2] = to_tf32(aStage[i].z);                              \
            As[ar][ac + 3] = to_tf32(aStage[i].w);                              \
            int br = idx >> 5, bc = (idx & 31) * 4;                             \
            Bs[br][bc + 0] = to_tf32(bStage[i].x);                              \
            Bs[br][bc + 1] = to_tf32(bStage[i].y);                              \
            Bs[br][bc + 2] = to_tf32(bStage[i].z);                              \
            Bs[br][bc + 3] = to_tf32(bStage[i].w);                              \
        }                                                                       \
    }

#define COMPUTE_CHUNK()                                                         \
    {                                                                           \
        _Pragma("unroll") for (int kk = 0; kk < 4; kk++) {                      \
            const int kb = kk * 8;                                              \
            float af[4][4];                                                     \
            _Pragma("unroll") for (int ma = 0; ma < 4; ma++) {                  \
                const int mr = wm + ma * 16 + gp;                               \
                af[ma][0] = As[mr][kb + tg];                                    \
                af[ma][1] = As[mr + 8][kb + tg];                                \
                af[ma][2] = As[mr][kb + tg + 4];                                \
                af[ma][3] = As[mr + 8][kb + tg + 4];                            \
            }                                                                   \
            float bf[4][2];                                                     \
            _Pragma("unroll") for (int nb = 0; nb < 4; nb++) {                  \
                const int nc = wn + nb * 8 + gp;                                \
                bf[nb][0] = Bs[kb + tg][nc];                                    \
                bf[nb][1] = Bs[kb + tg + 4][nc];                                \
            }                                                                   \
            _Pragma("unroll") for (int ma = 0; ma < 4; ma++)                    \
                _Pragma("unroll") for (int nb = 0; nb < 4; nb++)                \
                    mma_tf32(acc[ma][nb][0], acc[ma][nb][1], acc[ma][nb][2],    \
                             acc[ma][nb][3], af[ma][0], af[ma][1], af[ma][2],   \
                             af[ma][3], bf[nb][0], bf[nb][1]);                  \
        }                                                                       \
    }

    LOAD_STAGE(0);
    STORE_STAGE();
    __syncthreads();

    for (int k0 = GBK; k0 < K; k0 += GBK) {
        LOAD_STAGE(k0);
        COMPUTE_CHUNK();
        __syncthreads();
        STORE_STAGE();
        __syncthreads();
    }
    COMPUTE_CHUNK();

#pragma unroll
    for (int ma = 0; ma < 4; ma++) {
        const long r0 = bm + wm + ma * 16 + gp;
        const long r1 = r0 + 8;
#pragma unroll
        for (int nb = 0; nb < 4; nb++) {
            const int col = bn + wn + nb * 8 + tg * 2;
            float2 v0 = make_float2(acc[ma][nb][0], acc[ma][nb][1]);
            float2 v1 = make_float2(acc[ma][nb][2], acc[ma][nb][3]);
            if (BIAS) {
                const float bb0 = __ldg(bias + col), bb1 = __ldg(bias + col + 1);
                v0.x += bb0; v0.y += bb1;
                v1.x += bb0; v1.y += bb1;
            }
            *(float2*)(C + r0 * Ncols + col) = v0;
            *(float2*)(C + r1 * Ncols + col) = v1;
        }
    }
#undef LOAD_STAGE
#undef STORE_STAGE
#undef COMPUTE_CHUNK
}

// ---------------- positional softmax: pos[h,n,:] = softmax(rel@W_pos+b) --------
__global__ __launch_bounds__(256) void pos_kernel(const float* __restrict__ rel,
                                                  const float* __restrict__ Wp,
                                                  const float* __restrict__ bp,
                                                  float* __restrict__ pos) {
    const int n = blockIdx.x, h = blockIdx.y, tid = threadIdx.x;
    __shared__ float red[8];
    __shared__ float bcv;
    const float w0 = Wp[h], w1 = Wp[HH + h], w2 = Wp[2 * HH + h], bb = bp[h];
    const float* r = rel + (long)n * NN * 3;

    float s0, s1, s2 = -1e30f;
    {
        const float* p = r + tid * 3;
        s0 = p[0] * w0 + p[1] * w1 + p[2] * w2 + bb;
        p = r + (tid + 256) * 3;
        s1 = p[0] * w0 + p[1] * w1 + p[2] * w2 + bb;
        if (tid < 64) {
            p = r + (tid + 512) * 3;
            s2 = p[0] * w0 + p[1] * w1 + p[2] * w2 + bb;
        }
    }
    float mx = fmaxf(fmaxf(s0, s1), s2);
#pragma unroll
    for (int o = 16; o; o >>= 1) mx = fmaxf(mx, __shfl_xor_sync(~0u, mx, o));
    if ((tid & 31) == 0) red[tid >> 5] = mx;
    __syncthreads();
    if (tid == 0) {
        float m = red[0];
        for (int i = 1; i < 8; i++) m = fmaxf(m, red[i]);
        bcv = m;
    }
    __syncthreads();
    mx = bcv;
    float e0 = expf(s0 - mx), e1 = expf(s1 - mx);
    float e2 = (tid < 64) ? expf(s2 - mx) : 0.0f;
    float sum = e0 + e1 + e2;
#pragma unroll
    for (int o = 16; o; o >>= 1) sum += __shfl_xor_sync(~0u, sum, o);
    __syncthreads();
    if ((tid & 31) == 0) red[tid >> 5] = sum;
    __syncthreads();
    if (tid == 0) {
        float s = 0.f;
        for (int i = 0; i < 8; i++) s += red[i];
        bcv = 1.0f / s;
    }
    __syncthreads();
    const float inv = bcv;
    float* out = pos + ((long)h * NN + n) * NN;
    out[tid] = e0 * inv;
    out[tid + 256] = e1 * inv;
    if (tid < 64) out[tid + 512] = e2 * inv;
}

// ---------------- fused one-pass attention -------------------------------------
// Block = (b, h, 64 q-rows). Streams 9 k-tiles of 64. Per tile:
//   S = q@k^T (split-tf32), e = exp(S*scale) (no max-sub: logits bounded),
//   O_c += e @ v, O_p += pos @ v, l += rowsum(e).
// Final: out = (1-g)*O_c/l + g*O_p  (attn row-sum == 1, renorm drops).
// 8 warps = 4(m: 16 rows) x 2(k-half: 32 cols of S); partials combined via smem.
// smem: qs_hi/lo [64][68], ps [64][68], ks_hi/lo [64][72], vs [64][72] = 107520 B
#define QS 68
#define KS 72
#define FA_SMEM ((3 * 64 * QS + 3 * 64 * KS) * 4)

__global__ __launch_bounds__(256, 2) void fused_attn(
    const float* __restrict__ qk, const float* __restrict__ v,
    const float* __restrict__ pos, const float* __restrict__ gating,
    float* __restrict__ o) {
    extern __shared__ float smem[];
    float* qs_hi = smem;                    // [64][68]
    float* qs_lo = qs_hi + 64 * QS;
    float* ps    = qs_lo + 64 * QS;         // [64][68]
    float* ks_hi = ps + 64 * QS;            // [64][72] d-major
    float* ks_lo = ks_hi + 64 * KS;
    float* vs    = ks_lo + 64 * KS;         // [64][72] k-major

    const int tid = threadIdx.x, warp = tid >> 5, lane = tid & 31;
    const int gp = lane >> 2, tg = lane & 3;
    const int wm = (warp & 3) * 16;         // warp's 16 q-rows
    const int wh = warp >> 2;               // k-half (0/1): S cols wh*32..+32
    const int n0 = blockIdx.x * 64;
    const int b = blockIdx.y >> 4, h = blockIdx.y & 15;

    const float* qbase = qk + (long)b * NN * 2048 + h * 64;
    const float* kbase = qbase + 1024;
    const float* vbase = v + (long)b * NN * DD + h * 64;
    const float* pbase = pos + ((long)h * NN + n0) * NN;

    // ---- load q tile (hi/lo split) ----
    {
        int idx = tid;
#pragma unroll
        for (int i = 0; i < 4; i++, idx += 256) {
            int r = idx >> 4, c4 = (idx & 15) * 4;
            float4 a = *(const float4*)(qbase + (long)(n0 + r) * 2048 + c4);
            float h0 = to_tf32(a.x), h1 = to_tf32(a.y), h2 = to_tf32(a.z), h3 = to_tf32(a.w);
            qs_hi[r * QS + c4 + 0] = h0; qs_lo[r * QS + c4 + 0] = to_tf32(a.x - h0);
            qs_hi[r * QS + c4 + 1] = h1; qs_lo[r * QS + c4 + 1] = to_tf32(a.y - h1);
            qs_hi[r * QS + c4 + 2] = h2; qs_lo[r * QS + c4 + 2] = to_tf32(a.z - h2);
            qs_hi[r * QS + c4 + 3] = h3; qs_lo[r * QS + c4 + 3] = to_tf32(a.w - h3);
        }
    }

    float Oc[8][4], Op[8][4];
#pragma unroll
    for (int i = 0; i < 8; i++)
#pragma unroll
        for (int j = 0; j < 4; j++) { Oc[i][j] = 0.0f; Op[i][j] = 0.0f; }
    float l0 = 0.0f, l1 = 0.0f;
    const float scale = 0.125f;

    for (int m0 = 0; m0 < NN; m0 += 64) {
        __syncthreads();
        // ---- load k (hi/lo, transposed), v, pos tiles ----
        {
            int idx = tid;
#pragma unroll
            for (int i = 0; i < 4; i++, idx += 256) {
                int r = idx >> 4, c4 = (idx & 15) * 4;
                float4 a = *(const float4*)(kbase + (long)(m0 + r) * 2048 + c4);
                float h0 = to_tf32(a.x), h1 = to_tf32(a.y), h2 = to_tf32(a.z), h3 = to_tf32(a.w);
                ks_hi[(c4 + 0) * KS + r] = h0; ks_lo[(c4 + 0) * KS + r] = to_tf32(a.x - h0);
                ks_hi[(c4 + 1) * KS + r] = h1; ks_lo[(c4 + 1) * KS + r] = to_tf32(a.y - h1);
                ks_hi[(c4 + 2) * KS + r] = h2; ks_lo[(c4 + 2) * KS + r] = to_tf32(a.z - h2);
                ks_hi[(c4 + 3) * KS + r] = h3; ks_lo[(c4 + 3) * KS + r] = to_tf32(a.w - h3);
                float4 vv = *(const float4*)(vbase + (long)(m0 + r) * DD + c4);
                vs[r * KS + c4 + 0] = to_tf32(vv.x);
                vs[r * KS + c4 + 1] = to_tf32(vv.y);
                vs[r * KS + c4 + 2] = to_tf32(vv.z);
                vs[r * KS + c4 + 3] = to_tf32(vv.w);
                float4 pp = *(const float4*)(pbase + (long)r * NN + m0 + c4);
                ps[r * QS + c4 + 0] = to_tf32(pp.x);
                ps[r * QS + c4 + 1] = to_tf32(pp.y);
                ps[r * QS + c4 + 2] = to_tf32(pp.z);
                ps[r * QS + c4 + 3] = to_tf32(pp.w);
            }
        }
        __syncthreads();

        // ---- S = q @ k^T over this warp's 16x32 slice (split-tf32) ----
        float s[4][4];
#pragma unroll
        for (int i = 0; i < 4; i++)
#pragma unroll
            for (int j = 0; j < 4; j++) s[i][j] = 0.0f;

#pragma unroll
        for (int kk = 0; kk < 8; kk++) {
            const int kb = kk * 8;
            const int mr = wm + gp;
            float ah0 = qs_hi[mr * QS + kb + tg];
            float ah1 = qs_hi[(mr + 8) * QS + kb + tg];
            float ah2 = qs_hi[mr * QS + kb + tg + 4];
            float ah3 = qs_hi[(mr + 8) * QS + kb + tg + 4];
            float al0 = qs_lo[mr * QS + kb + tg];
            float al1 = qs_lo[(mr + 8) * QS + kb + tg];
            float al2 = qs_lo[mr * QS + kb + tg + 4];
            float al3 = qs_lo[(mr + 8) * QS + kb + tg + 4];
#pragma unroll
            for (int na = 0; na < 4; na++) {
                const int nc = wh * 32 + na * 8 + gp;
                float bh0 = ks_hi[(kb + tg) * KS + nc];
                float bh1 = ks_hi[(kb + tg + 4) * KS + nc];
                float bl0 = ks_lo[(kb + tg) * KS + nc];
                float bl1 = ks_lo[(kb + tg + 4) * KS + nc];
                mma_tf32(s[na][0], s[na][1], s[na][2], s[na][3],
                         ah0, ah1, ah2, ah3, bh0, bh1);
                mma_tf32(s[na][0], s[na][1], s[na][2], s[na][3],
                         ah0, ah1, ah2, ah3, bl0, bl1);
                mma_tf32(s[na][0], s[na][1], s[na][2], s[na][3],
                         al0, al1, al2, al3, bh0, bh1);
            }
        }

        // ---- exp (no max-sub), row-sum, tf32 round ----
        float p[4][4];
#pragma unroll
        for (int na = 0; na < 4; na++) {
            float e0 = __expf(s[na][0] * scale);
            float e1 = __expf(s[na][1] * scale);
            float e2 = __expf(s[na][2] * scale);
            float e3 = __expf(s[na][3] * scale);
            l0 += e0 + e1;
            l1 += e2 + e3;
            p[na][0] = to_tf32(e0); p[na][1] = to_tf32(e1);
            p[na][2] = to_tf32(e2); p[na][3] = to_tf32(e3);
        }

        // ---- remap exp(S) D-frags -> A-frags; accumulate O_c, O_p ----
        const int srcA = gp * 4 + (tg >> 1);
        const int srcB = srcA + 2;
        const bool odd = tg & 1;
#pragma unroll
        for (int ka = 0; ka < 4; ka++) {
            float t0, t1;
            t0 = __shfl_sync(~0u, p[ka][0], srcA);
            t1 = __shfl_sync(~0u, p[ka][1], srcA);
            float a0 = odd ? t1 : t0;
            t0 = __shfl_sync(~0u, p[ka][2], srcA);
            t1 = __shfl_sync(~0u, p[ka][3], srcA);
            float a1 = odd ? t1 : t0;
            t0 = __shfl_sync(~0u, p[ka][0], srcB);
            t1 = __shfl_sync(~0u, p[ka][1], srcB);
            float a2 = odd ? t1 : t0;
            t0 = __shfl_sync(~0u, p[ka][2], srcB);
            t1 = __shfl_sync(~0u, p[ka][3], srcB);
            float a3 = odd ? t1 : t0;

            const int pr = (wm + gp) * QS + wh * 32 + ka * 8 + tg;
            float pa0 = ps[pr];
            float pa1 = ps[pr + 8 * QS];
            float pa2 = ps[pr + 4];
            float pa3 = ps[pr + 8 * QS + 4];

            const int kr = (wh * 32 + ka * 8 + tg) * KS;
#pragma unroll
            for (int nv = 0; nv < 8; nv++) {
                float b0 = vs[kr + nv * 8 + gp];
                float b1 = vs[kr + 4 * KS + nv * 8 + gp];
                mma_tf32(Oc[nv][0], Oc[nv][1], Oc[nv][2], Oc[nv][3],
                         a0, a1, a2, a3, b0, b1);
                mma_tf32(Op[nv][0], Op[nv][1], Op[nv][2], Op[nv][3],
                         pa0, pa1, pa2, pa3, b0, b1);
            }
        }
    }

    // ---- reduce row-sums within tg group ----
    l0 += __shfl_xor_sync(~0u, l0, 1); l0 += __shfl_xor_sync(~0u, l0, 2);
    l1 += __shfl_xor_sync(~0u, l1, 1); l1 += __shfl_xor_sync(~0u, l1, 2);

    // ---- combine warp-half partials via smem (reuse ks/vs) ----
    __syncthreads();
    if (wh == 1) {
#pragma unroll
        for (int nv = 0; nv < 8; nv++) {
            const int base = (wm + gp) * KS + nv * 8 + 2 * tg;
            ks_hi[base]              = Oc[nv][0];
            ks_hi[base + 1]          = Oc[nv][1];
            ks_hi[base + 8 * KS]     = Oc[nv][2];
            ks_hi[base + 8 * KS + 1] = Oc[nv][3];
            ks_lo[base]              = Op[nv][0];
            ks_lo[base + 1]          = Op[nv][1];
            ks_lo[base + 8 * KS]     = Op[nv][2];
            ks_lo[base + 8 * KS + 1] = Op[nv][3];
        }
        vs[wm + gp] = l0;
        vs[wm + gp + 8] = l1;
    }
    __syncthreads();
    if (wh == 0) {
        const float g = 1.0f / (1.0f + __expf(-gating[h]));
        const float og = 1.0f - g;
        const float lt0 = l0 + vs[wm + gp];
        const float lt1 = l1 + vs[wm + gp + 8];
        const float c0 = og / lt0, c1 = og / lt1;
        const long row = n0 + wm + gp;
        float* dst0 = o + ((long)b * NN + row) * DD + h * 64;
#pragma unroll
        for (int nv = 0; nv < 8; nv++) {
            const int base = (wm + gp) * KS + nv * 8 + 2 * tg;
            float oc0 = Oc[nv][0] + ks_hi[base];
            float oc1 = Oc[nv][1] + ks_hi[base + 1];
            float oc2 = Oc[nv][2] + ks_hi[base + 8 * KS];
            float oc3 = Oc[nv][3] + ks_hi[base + 8 * KS + 1];
            float op0 = Op[nv][0] + ks_lo[base];
            float op1 = Op[nv][1] + ks_lo[base + 1];
            float op2 = Op[nv][2] + ks_lo[base + 8 * KS];
            float op3 = Op[nv][3] + ks_lo[base + 8 * KS + 1];
            float* dst = dst0 + nv * 8 + 2 * tg;
            *(float2*)dst = make_float2(c0 * oc0 + g * op0, c0 * oc1 + g * op1);
            *(float2*)(dst + 8L * DD) = make_float2(c1 * oc2 + g * op2, c1 * oc3 + g * op3);
        }
    }
}

// ---------------- launch ----------------
extern "C" void kernel_launch(void* const* d_in, const int* in_sizes, int n_in,
                              void* d_out, int out_size) {
    const float* x      = (const float*)d_in[0];
    const float* W_qk   = (const float*)d_in[1];
    const float* W_v    = (const float*)d_in[2];
    const float* W_proj = (const float*)d_in[3];
    const float* b_proj = (const float*)d_in[4];
    const float* W_pos  = (const float*)d_in[5];
    const float* b_pos  = (const float*)d_in[6];
    const float* gating = (const float*)d_in[7];
    const float* rel    = (const float*)d_in[8];
    float* out = (float*)d_out;

    float* qk;   cudaGetSymbolAddress((void**)&qk,   g_qk);
    float* vbuf; cudaGetSymbolAddress((void**)&vbuf, g_v);
    float* pos;  cudaGetSymbolAddress((void**)&pos,  g_pos);
    float* obuf; cudaGetSymbolAddress((void**)&obuf, g_o);

    cudaFuncSetAttribute(fused_attn, cudaFuncAttributeMaxDynamicSharedMemorySize, FA_SMEM);

    const int M = BB * NN;  // 9216

    // 1) qk = x @ W_qk
    gemm_tf32<false><<<dim3(2 * DD / 128, M / 128), 256>>>(x, W_qk, nullptr, qk, M, DD, 2 * DD);
    // 2) v = x @ W_v
    gemm_tf32<false><<<dim3(DD / 128, M / 128), 256>>>(x, W_v, nullptr, vbuf, M, DD, DD);
    // 3) positional softmax
    pos_kernel<<<dim3(NN, HH), 256>>>(rel, W_pos, b_pos, pos);
    // 4) fused one-pass attention
    fused_attn<<<dim3(NN / 64, BB * HH), 256, FA_SMEM>>>(qk, vbuf, pos, gating, obuf);
    // 5) out = o @ W_proj + b_proj
    gemm_tf32<true><<<dim3(DD / 128, M / 128), 256>>>(obuf, W_proj, b_proj, out, M, DD, DD);
}

// round 6
// speedup vs baseline: 3.3863x; 1.3550x over previous
#include <cuda_runtime.h>
#include <cuda_bf16.h>
#include <cstdint>

#define BB 16
#define NN 576
#define DD 1024
#define HH 16
#define HD 64

// ---------------- scratch (static device globals; no allocation) ----------------
__device__ float g_qk[(long)BB * NN * 2 * DD];        // [B,N,2D]
__device__ float g_v[(long)BB * NN * DD];             // [B,N,D]
__device__ float g_pos[(long)HH * NN * NN];           // [H,N,N]
__device__ float g_o[(long)BB * NN * DD];             // [B,N,D]

// ---------------- helpers ------------------------------------------------------
__device__ __forceinline__ float to_tf32(float x) {
    unsigned r;
    asm("cvt.rna.tf32.f32 %0, %1;" : "=r"(r) : "f"(x));
    return __uint_as_float(r);
}

__device__ __forceinline__ void mma_tf32(float& d0, float& d1, float& d2, float& d3,
                                         float a0, float a1, float a2, float a3,
                                         float b0, float b1) {
    asm volatile(
        "mma.sync.aligned.m16n8k8.row.col.f32.tf32.tf32.f32 "
        "{%0,%1,%2,%3}, {%4,%5,%6,%7}, {%8,%9}, {%0,%1,%2,%3};\n"
        : "+f"(d0), "+f"(d1), "+f"(d2), "+f"(d3)
        : "r"(__float_as_uint(a0)), "r"(__float_as_uint(a1)),
          "r"(__float_as_uint(a2)), "r"(__float_as_uint(a3)),
          "r"(__float_as_uint(b0)), "r"(__float_as_uint(b1)));
}

__device__ __forceinline__ void mma_bf16(float& d0, float& d1, float& d2, float& d3,
                                         unsigned a0, unsigned a1, unsigned a2, unsigned a3,
                                         unsigned b0, unsigned b1) {
    asm volatile(
        "mma.sync.aligned.m16n8k16.row.col.f32.bf16.bf16.f32 "
        "{%0,%1,%2,%3}, {%4,%5,%6,%7}, {%8,%9}, {%0,%1,%2,%3};\n"
        : "+f"(d0), "+f"(d1), "+f"(d2), "+f"(d3)
        : "r"(a0), "r"(a1), "r"(a2), "r"(a3), "r"(b0), "r"(b1));
}

__device__ __forceinline__ unsigned packbf2(__nv_bfloat16 x, __nv_bfloat16 y) {
    __nv_bfloat162 t;
    t.x = x; t.y = y;
    return *reinterpret_cast<unsigned*>(&t);
}

// ---------------- tf32 GEMM, double-buffered smem ------------------------------
#define GBM 128
#define GBN 128
#define GBK 32
#define AS_STRIDE 36
#define BS_STRIDE 136
#define AS_STAGE (GBM * AS_STRIDE)           // 4608
#define BS_STAGE (GBK * BS_STRIDE)           // 4352
#define GS_SMEM ((2 * AS_STAGE + 2 * BS_STAGE) * 4)   // 71680 B

template <bool BIAS>
__global__ __launch_bounds__(256, 2) void gemm_tf32(const float* __restrict__ A,
                                                    const float* __restrict__ W,
                                                    const float* __restrict__ bias,
                                                    float* __restrict__ C,
                                                    int M, int K, int Ncols) {
    extern __shared__ float gsm[];
    float* As0 = gsm;                        // 2 stages [128][36]
    float* Bs0 = gsm + 2 * AS_STAGE;         // 2 stages [32][136]

    const int tid = threadIdx.x;
    const int warp = tid >> 5, lane = tid & 31;
    const int wm = (warp & 1) * 64;
    const int wn = (warp >> 1) * 32;
    const int gp = lane >> 2, tg = lane & 3;

    const int bm = blockIdx.y * GBM, bn = blockIdx.x * GBN;

    float acc[4][4][4];
#pragma unroll
    for (int i = 0; i < 4; i++)
#pragma unroll
        for (int j = 0; j < 4; j++)
#pragma unroll
            for (int r = 0; r < 4; r++) acc[i][j][r] = 0.0f;

    float4 aStage[4], bStage[4];
    const float* Abase = A + (long)bm * K;
    const float* Wbase = W + bn;

#define LOAD_STAGE(k0)                                                          \
    {                                                                           \
        _Pragma("unroll") for (int i = 0; i < 4; i++) {                         \
            int idx = tid + 256 * i;                                            \
            aStage[i] = *(const float4*)(Abase + (long)(idx >> 3) * K + (k0) +  \
                                         (idx & 7) * 4);                        \
            bStage[i] = *(const float4*)(Wbase + (long)((k0) + (idx >> 5)) *    \
                                         Ncols + (idx & 31) * 4);               \
        }                                                                       \
    }

#define STORE_STAGE(s)                                                          \
    {                                                                           \
        float* Ad = As0 + (s) * AS_STAGE;                                       \
        float* Bd = Bs0 + (s) * BS_STAGE;                                       \
        _Pragma("unroll") for (int i = 0; i < 4; i++) {                         \
            int idx = tid + 256 * i;                                            \
            int ar = idx >> 3, ac = (idx & 7) * 4;                              \
            Ad[ar * AS_STRIDE + ac + 0] = to_tf32(aStage[i].x);                 \
            Ad[ar * AS_STRIDE + ac + 1] = to_tf32(aStage[i].y);                 \
            Ad[ar * AS_STRIDE + ac + 2] = to_tf32(aStage[i].z);                 \
            Ad[ar * AS_STRIDE + ac + 3] = to_tf32(aStage[i].w);                 \
            int br = idx >> 5, bc = (idx & 31) * 4;                             \
            Bd[br * BS_STRIDE + bc + 0] = to_tf32(bStage[i].x);                 \
            Bd[br * BS_STRIDE + bc + 1] = to_tf32(bStage[i].y);                 \
            Bd[br * BS_STRIDE + bc + 2] = to_tf32(bStage[i].z);                 \
            Bd[br * BS_STRIDE + bc + 3] = to_tf32(bStage[i].w);                 \
        }                                                                       \
    }

#define COMPUTE_CHUNK(s)                                                        \
    {                                                                           \
        const float* Ar = As0 + (s) * AS_STAGE;                                 \
        const float* Br = Bs0 + (s) * BS_STAGE;                                 \
        _Pragma("unroll") for (int kk = 0; kk < 4; kk++) {                      \
            const int kb = kk * 8;                                              \
            float af[4][4];                                                     \
            _Pragma("unroll") for (int ma = 0; ma < 4; ma++) {                  \
                const int mr = wm + ma * 16 + gp;                               \
                af[ma][0] = Ar[mr * AS_STRIDE + kb + tg];                       \
                af[ma][1] = Ar[(mr + 8) * AS_STRIDE + kb + tg];                 \
                af[ma][2] = Ar[mr * AS_STRIDE + kb + tg + 4];                   \
                af[ma][3] = Ar[(mr + 8) * AS_STRIDE + kb + tg + 4];             \
            }                                                                   \
            float bf[4][2];                                                     \
            _Pragma("unroll") for (int nb = 0; nb < 4; nb++) {                  \
                const int nc = wn + nb * 8 + gp;                                \
                bf[nb][0] = Br[(kb + tg) * BS_STRIDE + nc];                     \
                bf[nb][1] = Br[(kb + tg + 4) * BS_STRIDE + nc];                 \
            }                                                                   \
            _Pragma("unroll") for (int ma = 0; ma < 4; ma++)                    \
                _Pragma("unroll") for (int nb = 0; nb < 4; nb++)                \
                    mma_tf32(acc[ma][nb][0], acc[ma][nb][1], acc[ma][nb][2],    \
                             acc[ma][nb][3], af[ma][0], af[ma][1], af[ma][2],   \
                             af[ma][3], bf[nb][0], bf[nb][1]);                  \
        }                                                                       \
    }

    int s = 0;
    LOAD_STAGE(0);
    STORE_STAGE(0);
    __syncthreads();

    for (int k0 = GBK; k0 < K; k0 += GBK) {
        LOAD_STAGE(k0);
        COMPUTE_CHUNK(s);
        STORE_STAGE(s ^ 1);
        s ^= 1;
        __syncthreads();
    }
    COMPUTE_CHUNK(s);

#pragma unroll
    for (int ma = 0; ma < 4; ma++) {
        const long r0 = bm + wm + ma * 16 + gp;
        const long r1 = r0 + 8;
#pragma unroll
        for (int nb = 0; nb < 4; nb++) {
            const int col = bn + wn + nb * 8 + tg * 2;
            float2 v0 = make_float2(acc[ma][nb][0], acc[ma][nb][1]);
            float2 v1 = make_float2(acc[ma][nb][2], acc[ma][nb][3]);
            if (BIAS) {
                const float bb0 = __ldg(bias + col), bb1 = __ldg(bias + col + 1);
                v0.x += bb0; v0.y += bb1;
                v1.x += bb0; v1.y += bb1;
            }
            *(float2*)(C + r0 * Ncols + col) = v0;
            *(float2*)(C + r1 * Ncols + col) = v1;
        }
    }
#undef LOAD_STAGE
#undef STORE_STAGE
#undef COMPUTE_CHUNK
}

// ---------------- positional softmax: pos[h,n,:] = softmax(rel@W_pos+b) --------
__global__ __launch_bounds__(256) void pos_kernel(const float* __restrict__ rel,
                                                  const float* __restrict__ Wp,
                                                  const float* __restrict__ bp,
                                                  float* __restrict__ pos) {
    const int n = blockIdx.x, h = blockIdx.y, tid = threadIdx.x;
    __shared__ float red[8];
    __shared__ float bcv;
    const float w0 = Wp[h], w1 = Wp[HH + h], w2 = Wp[2 * HH + h], bb = bp[h];
    const float* r = rel + (long)n * NN * 3;

    float s0, s1, s2 = -1e30f;
    {
        const float* p = r + tid * 3;
        s0 = p[0] * w0 + p[1] * w1 + p[2] * w2 + bb;
        p = r + (tid + 256) * 3;
        s1 = p[0] * w0 + p[1] * w1 + p[2] * w2 + bb;
        if (tid < 64) {
            p = r + (tid + 512) * 3;
            s2 = p[0] * w0 + p[1] * w1 + p[2] * w2 + bb;
        }
    }
    float mx = fmaxf(fmaxf(s0, s1), s2);
#pragma unroll
    for (int o = 16; o; o >>= 1) mx = fmaxf(mx, __shfl_xor_sync(~0u, mx, o));
    if ((tid & 31) == 0) red[tid >> 5] = mx;
    __syncthreads();
    if (tid == 0) {
        float m = red[0];
        for (int i = 1; i < 8; i++) m = fmaxf(m, red[i]);
        bcv = m;
    }
    __syncthreads();
    mx = bcv;
    float e0 = expf(s0 - mx), e1 = expf(s1 - mx);
    float e2 = (tid < 64) ? expf(s2 - mx) : 0.0f;
    float sum = e0 + e1 + e2;
#pragma unroll
    for (int o = 16; o; o >>= 1) sum += __shfl_xor_sync(~0u, sum, o);
    __syncthreads();
    if ((tid & 31) == 0) red[tid >> 5] = sum;
    __syncthreads();
    if (tid == 0) {
        float s = 0.f;
        for (int i = 0; i < 8; i++) s += red[i];
        bcv = 1.0f / s;
    }
    __syncthreads();
    const float inv = bcv;
    float* out = pos + ((long)h * NN + n) * NN;
    out[tid] = e0 * inv;
    out[tid + 256] = e1 * inv;
    if (tid < 64) out[tid + 512] = e2 * inv;
}

// ---------------- fused one-pass attention -------------------------------------
// Block = (b, h, 64 q-rows). S-phase: split-bf16 m16n8k16 (qh*kh + qh*kl + ql*kh).
// exp (no max-sub; logits bounded), O_c += e@v (tf32), O_p += pos@v (tf32),
// l += rowsum(e). Final: out = (1-g)*O_c/l + g*O_p.
// smem: qsb_h/l, ksb_h/l [64][36] b32-pairs; vs [64][72] f32; ps [64][68] f32.
#define QB 36
#define KS 72
#define QS 68
#define FA_SMEM ((4 * 64 * QB + 64 * KS + 64 * QS) * 4)   // 72704 B

__global__ __launch_bounds__(256, 2) void fused_attn(
    const float* __restrict__ qk, const float* __restrict__ v,
    const float* __restrict__ pos, const float* __restrict__ gating,
    float* __restrict__ o) {
    extern __shared__ float smem[];
    unsigned* qsb_h = (unsigned*)smem;          // [64][36] bf16x2 (d-pairs)
    unsigned* qsb_l = qsb_h + 64 * QB;
    unsigned* ksb_h = qsb_l + 64 * QB;          // [64][36] rows = seq
    unsigned* ksb_l = ksb_h + 64 * QB;
    float* vs = (float*)(ksb_l + 64 * QB);      // [64][72]
    float* ps = vs + 64 * KS;                   // [64][68]

    const int tid = threadIdx.x, warp = tid >> 5, lane = tid & 31;
    const int gp = lane >> 2, tg = lane & 3;
    const int wm = (warp & 3) * 16;             // warp's 16 q-rows
    const int wh = warp >> 2;                   // k-half (S cols wh*32..+32)
    const int n0 = blockIdx.x * 64;
    const int b = blockIdx.y >> 4, h = blockIdx.y & 15;

    const float* qbase = qk + (long)b * NN * 2048 + h * 64;
    const float* kbase = qbase + 1024;
    const float* vbase = v + (long)b * NN * DD + h * 64;
    const float* pbase = pos + ((long)h * NN + n0) * NN;

    // ---- load q tile (bf16 hi/lo split, packed pairs) ----
    {
        int idx = tid;
#pragma unroll
        for (int i = 0; i < 4; i++, idx += 256) {
            int r = idx >> 4, c4 = (idx & 15) * 4;
            float4 a = *(const float4*)(qbase + (long)(n0 + r) * 2048 + c4);
            __nv_bfloat16 h0 = __float2bfloat16_rn(a.x);
            __nv_bfloat16 h1 = __float2bfloat16_rn(a.y);
            __nv_bfloat16 h2 = __float2bfloat16_rn(a.z);
            __nv_bfloat16 h3 = __float2bfloat16_rn(a.w);
            qsb_h[r * QB + (c4 >> 1)]     = packbf2(h0, h1);
            qsb_h[r * QB + (c4 >> 1) + 1] = packbf2(h2, h3);
            qsb_l[r * QB + (c4 >> 1)]     = packbf2(
                __float2bfloat16_rn(a.x - __bfloat162float(h0)),
                __float2bfloat16_rn(a.y - __bfloat162float(h1)));
            qsb_l[r * QB + (c4 >> 1) + 1] = packbf2(
                __float2bfloat16_rn(a.z - __bfloat162float(h2)),
                __float2bfloat16_rn(a.w - __bfloat162float(h3)));
        }
    }

    float Oc[8][4], Op[8][4];
#pragma unroll
    for (int i = 0; i < 8; i++)
#pragma unroll
        for (int j = 0; j < 4; j++) { Oc[i][j] = 0.0f; Op[i][j] = 0.0f; }
    float l0 = 0.0f, l1 = 0.0f;
    const float scale = 0.125f;

    for (int m0 = 0; m0 < NN; m0 += 64) {
        __syncthreads();
        // ---- load k (bf16 hi/lo), v (tf32), pos (tf32) tiles ----
        {
            int idx = tid;
#pragma unroll
            for (int i = 0; i < 4; i++, idx += 256) {
                int r = idx >> 4, c4 = (idx & 15) * 4;
                float4 a = *(const float4*)(kbase + (long)(m0 + r) * 2048 + c4);
                __nv_bfloat16 h0 = __float2bfloat16_rn(a.x);
                __nv_bfloat16 h1 = __float2bfloat16_rn(a.y);
                __nv_bfloat16 h2 = __float2bfloat16_rn(a.z);
                __nv_bfloat16 h3 = __float2bfloat16_rn(a.w);
                ksb_h[r * QB + (c4 >> 1)]     = packbf2(h0, h1);
                ksb_h[r * QB + (c4 >> 1) + 1] = packbf2(h2, h3);
                ksb_l[r * QB + (c4 >> 1)]     = packbf2(
                    __float2bfloat16_rn(a.x - __bfloat162float(h0)),
                    __float2bfloat16_rn(a.y - __bfloat162float(h1)));
                ksb_l[r * QB + (c4 >> 1) + 1] = packbf2(
                    __float2bfloat16_rn(a.z - __bfloat162float(h2)),
                    __float2bfloat16_rn(a.w - __bfloat162float(h3)));
                float4 vv = *(const float4*)(vbase + (long)(m0 + r) * DD + c4);
                vs[r * KS + c4 + 0] = to_tf32(vv.x);
                vs[r * KS + c4 + 1] = to_tf32(vv.y);
                vs[r * KS + c4 + 2] = to_tf32(vv.z);
                vs[r * KS + c4 + 3] = to_tf32(vv.w);
                float4 pp = *(const float4*)(pbase + (long)r * NN + m0 + c4);
                ps[r * QS + c4 + 0] = to_tf32(pp.x);
                ps[r * QS + c4 + 1] = to_tf32(pp.y);
                ps[r * QS + c4 + 2] = to_tf32(pp.z);
                ps[r * QS + c4 + 3] = to_tf32(pp.w);
            }
        }
        __syncthreads();

        // ---- S = q @ k^T over warp's 16x32 slice (split-bf16, m16n8k16) ----
        float s[4][4];
#pragma unroll
        for (int i = 0; i < 4; i++)
#pragma unroll
            for (int j = 0; j < 4; j++) s[i][j] = 0.0f;

        const int rowA = (wm + gp) * QB;
#pragma unroll
        for (int kc = 0; kc < 4; kc++) {
            const int d2 = kc * 8 + tg;
            unsigned ah0 = qsb_h[rowA + d2];
            unsigned ah1 = qsb_h[rowA + 8 * QB + d2];
            unsigned ah2 = qsb_h[rowA + d2 + 4];
            unsigned ah3 = qsb_h[rowA + 8 * QB + d2 + 4];
            unsigned al0 = qsb_l[rowA + d2];
            unsigned al1 = qsb_l[rowA + 8 * QB + d2];
            unsigned al2 = qsb_l[rowA + d2 + 4];
            unsigned al3 = qsb_l[rowA + 8 * QB + d2 + 4];
#pragma unroll
            for (int na = 0; na < 4; na++) {
                const int rowB = (wh * 32 + na * 8 + gp) * QB;
                unsigned bh0 = ksb_h[rowB + d2];
                unsigned bh1 = ksb_h[rowB + d2 + 4];
                unsigned bl0 = ksb_l[rowB + d2];
                unsigned bl1 = ksb_l[rowB + d2 + 4];
                mma_bf16(s[na][0], s[na][1], s[na][2], s[na][3],
                         ah0, ah1, ah2, ah3, bh0, bh1);
                mma_bf16(s[na][0], s[na][1], s[na][2], s[na][3],
                         ah0, ah1, ah2, ah3, bl0, bl1);
                mma_bf16(s[na][0], s[na][1], s[na][2], s[na][3],
                         al0, al1, al2, al3, bh0, bh1);
            }
        }

        // ---- exp (no max-sub), row-sum, tf32 round ----
        float p[4][4];
#pragma unroll
        for (int na = 0; na < 4; na++) {
            float e0 = __expf(s[na][0] * scale);
            float e1 = __expf(s[na][1] * scale);
            float e2 = __expf(s[na][2] * scale);
            float e3 = __expf(s[na][3] * scale);
            l0 += e0 + e1;
            l1 += e2 + e3;
            p[na][0] = to_tf32(e0); p[na][1] = to_tf32(e1);
            p[na][2] = to_tf32(e2); p[na][3] = to_tf32(e3);
        }

        // ---- remap exp(S) D-frags -> A-frags; accumulate O_c, O_p (tf32) ----
        const int srcA = gp * 4 + (tg >> 1);
        const int srcB = srcA + 2;
        const bool odd = tg & 1;
#pragma unroll
        for (int ka = 0; ka < 4; ka++) {
            float t0, t1;
            t0 = __shfl_sync(~0u, p[ka][0], srcA);
            t1 = __shfl_sync(~0u, p[ka][1], srcA);
            float a0 = odd ? t1 : t0;
            t0 = __shfl_sync(~0u, p[ka][2], srcA);
            t1 = __shfl_sync(~0u, p[ka][3], srcA);
            float a1 = odd ? t1 : t0;
            t0 = __shfl_sync(~0u, p[ka][0], srcB);
            t1 = __shfl_sync(~0u, p[ka][1], srcB);
            float a2 = odd ? t1 : t0;
            t0 = __shfl_sync(~0u, p[ka][2], srcB);
            t1 = __shfl_sync(~0u, p[ka][3], srcB);
            float a3 = odd ? t1 : t0;

            const int pr = (wm + gp) * QS + wh * 32 + ka * 8 + tg;
            float pa0 = ps[pr];
            float pa1 = ps[pr + 8 * QS];
            float pa2 = ps[pr + 4];
            float pa3 = ps[pr + 8 * QS + 4];

            const int kr = (wh * 32 + ka * 8 + tg) * KS;
#pragma unroll
            for (int nv = 0; nv < 8; nv++) {
                float b0 = vs[kr + nv * 8 + gp];
                float b1 = vs[kr + 4 * KS + nv * 8 + gp];
                mma_tf32(Oc[nv][0], Oc[nv][1], Oc[nv][2], Oc[nv][3],
                         a0, a1, a2, a3, b0, b1);
                mma_tf32(Op[nv][0], Op[nv][1], Op[nv][2], Op[nv][3],
                         pa0, pa1, pa2, pa3, b0, b1);
            }
        }
    }

    // ---- reduce row-sums within tg group ----
    l0 += __shfl_xor_sync(~0u, l0, 1); l0 += __shfl_xor_sync(~0u, l0, 2);
    l1 += __shfl_xor_sync(~0u, l1, 1); l1 += __shfl_xor_sync(~0u, l1, 2);

    // ---- combine warp-half partials (reuse vs, ps, qsb_h as scratch) ----
    float* lbuf = (float*)qsb_h;
    __syncthreads();
    if (wh == 1) {
#pragma unroll
        for (int nv = 0; nv < 8; nv++) {
            const int bc = (wm + gp) * KS + nv * 8 + 2 * tg;
            vs[bc]              = Oc[nv][0];
            vs[bc + 1]          = Oc[nv][1];
            vs[bc + 8 * KS]     = Oc[nv][2];
            vs[bc + 8 * KS + 1] = Oc[nv][3];
            const int bp = (wm + gp) * QS + nv * 8 + 2 * tg;
            ps[bp]              = Op[nv][0];
            ps[bp + 1]          = Op[nv][1];
            ps[bp + 8 * QS]     = Op[nv][2];
            ps[bp + 8 * QS + 1] = Op[nv][3];
        }
        lbuf[wm + gp] = l0;
        lbuf[wm + gp + 8] = l1;
    }
    __syncthreads();
    if (wh == 0) {
        const float g = 1.0f / (1.0f + __expf(-gating[h]));
        const float og = 1.0f - g;
        const float lt0 = l0 + lbuf[wm + gp];
        const float lt1 = l1 + lbuf[wm + gp + 8];
        const float c0 = og / lt0, c1 = og / lt1;
        const long row = n0 + wm + gp;
        float* dst0 = o + ((long)b * NN + row) * DD + h * 64;
#pragma unroll
        for (int nv = 0; nv < 8; nv++) {
            const int bc = (wm + gp) * KS + nv * 8 + 2 * tg;
            const int bp = (wm + gp) * QS + nv * 8 + 2 * tg;
            float oc0 = Oc[nv][0] + vs[bc];
            float oc1 = Oc[nv][1] + vs[bc + 1];
            float oc2 = Oc[nv][2] + vs[bc + 8 * KS];
            float oc3 = Oc[nv][3] + vs[bc + 8 * KS + 1];
            float op0 = Op[nv][0] + ps[bp];
            float op1 = Op[nv][1] + ps[bp + 1];
            float op2 = Op[nv][2] + ps[bp + 8 * QS];
            float op3 = Op[nv][3] + ps[bp + 8 * QS + 1];
            float* dst = dst0 + nv * 8 + 2 * tg;
            *(float2*)dst = make_float2(c0 * oc0 + g * op0, c0 * oc1 + g * op1);
            *(float2*)(dst + 8L * DD) = make_float2(c1 * oc2 + g * op2, c1 * oc3 + g * op3);
        }
    }
}

// ---------------- launch ----------------
extern "C" void kernel_launch(void* const* d_in, const int* in_sizes, int n_in,
                              void* d_out, int out_size) {
    const float* x      = (const float*)d_in[0];
    const float* W_qk   = (const float*)d_in[1];
    const float* W_v    = (const float*)d_in[2];
    const float* W_proj = (const float*)d_in[3];
    const float* b_proj = (const float*)d_in[4];
    const float* W_pos  = (const float*)d_in[5];
    const float* b_pos  = (const float*)d_in[6];
    const float* gating = (const float*)d_in[7];
    const float* rel    = (const float*)d_in[8];
    float* out = (float*)d_out;

    float* qk;   cudaGetSymbolAddress((void**)&qk,   g_qk);
    float* vbuf; cudaGetSymbolAddress((void**)&vbuf, g_v);
    float* pos;  cudaGetSymbolAddress((void**)&pos,  g_pos);
    float* obuf; cudaGetSymbolAddress((void**)&obuf, g_o);

    cudaFuncSetAttribute(gemm_tf32<false>, cudaFuncAttributeMaxDynamicSharedMemorySize, GS_SMEM);
    cudaFuncSetAttribute(gemm_tf32<true>,  cudaFuncAttributeMaxDynamicSharedMemorySize, GS_SMEM);
    cudaFuncSetAttribute(fused_attn, cudaFuncAttributeMaxDynamicSharedMemorySize, FA_SMEM);

    const int M = BB * NN;  // 9216

    // 1) qk = x @ W_qk
    gemm_tf32<false><<<dim3(2 * DD / 128, M / 128), 256, GS_SMEM>>>(x, W_qk, nullptr, qk, M, DD, 2 * DD);
    // 2) v = x @ W_v
    gemm_tf32<false><<<dim3(DD / 128, M / 128), 256, GS_SMEM>>>(x, W_v, nullptr, vbuf, M, DD, DD);
    // 3) positional softmax
    pos_kernel<<<dim3(NN, HH), 256>>>(rel, W_pos, b_pos, pos);
    // 4) fused one-pass attention
    fused_attn<<<dim3(NN / 64, BB * HH), 256, FA_SMEM>>>(qk, vbuf, pos, gating, obuf);
    // 5) out = o @ W_proj + b_proj
    gemm_tf32<true><<<dim3(DD / 128, M / 128), 256, GS_SMEM>>>(obuf, W_proj, b_proj, out, M, DD, DD);
}